// round 7
// baseline (speedup 1.0000x reference)
#include <cuda_runtime.h>
#include <cuda_bf16.h>
#include <cstdint>

// Problem constants (fixed by the reference)
#define NTOK   8192
#define DMODEL 1024
#define DHID   4096
#define NEXP   8
#define CAP    2048

// ---------------- scratch (allocation-free: __device__ globals) ------------
__device__ int   g_route[NTOK];
__device__ int   g_toklist[NEXP * CAP];
__device__ int   g_count[NEXP];

// bf16 hi/lo planes (same layouts as the fp32 originals; NO transposes)
__device__ __align__(16) __nv_bfloat16 g_xHi[(size_t)NTOK * DMODEL];
__device__ __align__(16) __nv_bfloat16 g_xLo[(size_t)NTOK * DMODEL];
__device__ __align__(16) __nv_bfloat16 g_w1Hi[(size_t)NEXP * DMODEL * DHID]; // [e][k][n]
__device__ __align__(16) __nv_bfloat16 g_w1Lo[(size_t)NEXP * DMODEL * DHID];
__device__ __align__(16) __nv_bfloat16 g_w2Hi[(size_t)NEXP * DHID * DMODEL]; // [e][k][n]
__device__ __align__(16) __nv_bfloat16 g_w2Lo[(size_t)NEXP * DHID * DMODEL];
__device__ __align__(16) __nv_bfloat16 g_hHi[(size_t)NEXP * CAP * DHID];     // [e][row][k]
__device__ __align__(16) __nv_bfloat16 g_hLo[(size_t)NEXP * CAP * DHID];

// ---------------- PTX helpers ----------------------------------------------
__device__ __forceinline__ uint32_t smem_u32(const void* p) {
    return (uint32_t)__cvta_generic_to_shared(p);
}

__device__ __forceinline__ void mma_bf16(float* c, const uint32_t* a, const uint32_t* b) {
    asm volatile(
        "mma.sync.aligned.m16n8k16.row.col.f32.bf16.bf16.f32 "
        "{%0,%1,%2,%3}, {%4,%5,%6,%7}, {%8,%9}, {%0,%1,%2,%3};"
        : "+f"(c[0]), "+f"(c[1]), "+f"(c[2]), "+f"(c[3])
        : "r"(a[0]), "r"(a[1]), "r"(a[2]), "r"(a[3]), "r"(b[0]), "r"(b[1]));
}

__device__ __forceinline__ void ldsm_x4_t(uint32_t& r0, uint32_t& r1,
                                          uint32_t& r2, uint32_t& r3, uint32_t addr) {
    asm volatile("ldmatrix.sync.aligned.m8n8.x4.trans.shared.b16 {%0,%1,%2,%3}, [%4];"
        : "=r"(r0), "=r"(r1), "=r"(r2), "=r"(r3) : "r"(addr));
}

// B tile byte offset with XOR swizzle (k row = 256B; spread bits[6:4] by k&7)
__device__ __forceinline__ uint32_t bswz(int k, int nbyte) {
    return (uint32_t)(k * 256 + (nbyte ^ ((k & 7) << 4)));
}

// ---------------- router: logits + argmax (top_k = 1) ---------------------
__global__ __launch_bounds__(256) void moe_router(const float* __restrict__ x,
                                                  const float* __restrict__ Wg,
                                                  const float* __restrict__ bg) {
    __shared__ float sWgT[NEXP][DMODEL];
    int tid = threadIdx.x;
    for (int i = tid; i < DMODEL * NEXP; i += 256) {
        int d = i >> 3, e = i & 7;
        sWgT[e][d] = Wg[i];
    }
    __syncthreads();

    int wid = tid >> 5, lane = tid & 31;
    int token = blockIdx.x * 8 + wid;
    const float* xr = x + (size_t)token * DMODEL;

    float acc[NEXP];
#pragma unroll
    for (int e = 0; e < NEXP; e++) acc[e] = 0.f;
    for (int d = lane; d < DMODEL; d += 32) {
        float xv = xr[d];
#pragma unroll
        for (int e = 0; e < NEXP; e++) acc[e] += xv * sWgT[e][d];
    }
#pragma unroll
    for (int e = 0; e < NEXP; e++) {
#pragma unroll
        for (int off = 16; off > 0; off >>= 1)
            acc[e] += __shfl_xor_sync(0xffffffffu, acc[e], off);
    }
    if (lane == 0) {
        int best = 0;
        float bv = acc[0] + bg[0];
#pragma unroll
        for (int e = 1; e < NEXP; e++) {
            float v = acc[e] + bg[e];
            if (v > bv) { bv = v; best = e; }   // first-max tie-break
        }
        g_route[token] = best;
    }
}

// ---------------- ordered capacity scan ------------------------------------
__global__ __launch_bounds__(256) void moe_scan() {
    int tid = threadIdx.x;
    for (int i = tid; i < NEXP * CAP; i += 256) g_toklist[i] = -1;
    __syncthreads();
    int wid = tid >> 5, lane = tid & 31;   // wid == expert id
    int base = 0;
    for (int c = 0; c < NTOK / 32; c++) {
        int token = c * 32 + lane;
        int r = g_route[token];
        unsigned mask = __ballot_sync(0xffffffffu, r == wid);
        if (r == wid) {
            int pos = base + __popc(mask & ((1u << lane) - 1u));
            if (pos < CAP) g_toklist[wid * CAP + pos] = token;
        }
        base += __popc(mask);
    }
    if (lane == 0) g_count[wid] = base < CAP ? base : CAP;
}

// ---------------- fp32 -> bf16 hi/lo (destination chosen DEVICE-SIDE) -------
// CRITICAL: __device__ array symbols must never be passed as kernel args from
// host code (host shadow address + GB300 ATS silently writes host memory).
__global__ __launch_bounds__(256) void convert_plane(const float* __restrict__ src,
                                                     int which) {
    __nv_bfloat16 *dHi, *dLo;
    if (which == 0)      { dHi = g_xHi;  dLo = g_xLo;  }
    else if (which == 1) { dHi = g_w1Hi; dLo = g_w1Lo; }
    else                 { dHi = g_w2Hi; dLo = g_w2Lo; }

    size_t i = ((size_t)blockIdx.x * 256 + threadIdx.x) * 4;
    float4 v = *(const float4*)(src + i);
    __nv_bfloat16 h0 = __float2bfloat16(v.x), h1 = __float2bfloat16(v.y);
    __nv_bfloat16 h2 = __float2bfloat16(v.z), h3 = __float2bfloat16(v.w);
    __nv_bfloat16 l0 = __float2bfloat16(v.x - __bfloat162float(h0));
    __nv_bfloat16 l1 = __float2bfloat16(v.y - __bfloat162float(h1));
    __nv_bfloat16 l2 = __float2bfloat16(v.z - __bfloat162float(h2));
    __nv_bfloat16 l3 = __float2bfloat16(v.w - __bfloat162float(h3));
    __nv_bfloat162 H0 = {h0, h1}, H1 = {h2, h3}, L0 = {l0, l1}, L1 = {l2, l3};
    *(uint2*)(dHi + i) = make_uint2(*(uint32_t*)&H0, *(uint32_t*)&H1);
    *(uint2*)(dLo + i) = make_uint2(*(uint32_t*)&L0, *(uint32_t*)&L1);
}

// ---------------- 3xBF16 tensor-core GEMMs (Round-3 structure) --------------
// Block tile 128x128, BK=32. 8 warps: 4 in M x 2 in N; warp 32x64 via
// 2 m16 x 8 n8 tiles of mma.m16n8k16.bf16, 3 mma per tile (hi*hi+lo*hi+hi*lo).
// Operands come pre-split from global bf16 planes: mainloop has NO conversions.

#define BM 128
#define BN 128
#define BK 32
#define A_STRIDE 40   // bf16 units per A row (80B): R3-validated conflict-free

template <int MODE>
__global__ __launch_bounds__(256, 1) void moe_ffn(const float* __restrict__ bias_g,
                                                  float* __restrict__ outg) {
    const int Ktot = (MODE == 0) ? DMODEL : DHID;
    const int Ntot = (MODE == 0) ? DHID : DMODEL;

    int e = blockIdx.z;
    int count = g_count[e];
    int rowBase = blockIdx.y * BM;
    if (rowBase >= count) return;
    int colBase = blockIdx.x * BN;

    __shared__ __align__(16) __nv_bfloat16 AsHi[BM * A_STRIDE];
    __shared__ __align__(16) __nv_bfloat16 AsLo[BM * A_STRIDE];
    __shared__ __align__(16) __nv_bfloat16 BsHi[BK * BN];   // [k][n] swizzled, 256B rows
    __shared__ __align__(16) __nv_bfloat16 BsLo[BK * BN];
    __shared__ int sTok[BM];

    int tid = threadIdx.x;
    for (int i = tid; i < BM; i += 256) {
        int row = rowBase + i;
        sTok[i] = (row < count) ? g_toklist[e * CAP + row] : -1;
    }
    __syncthreads();

    const float* bias = bias_g + (size_t)e * Ntot + colBase;

    int warpId = tid >> 5, lane = tid & 31;
    int warpM = warpId & 3;            // M offset *32
    int warpN = warpId >> 2;           // N offset *64
    int gid = lane >> 2, tig = lane & 3;

    uint32_t bHiBase = smem_u32(BsHi);
    uint32_t bLoBase = smem_u32(BsLo);
    int lm_m  = lane >> 3;
    int lm_rr = lane & 7;
    int lm_kd = (lm_m & 1) * 8 + lm_rr;
    int lm_nd = (lm_m >> 1) * 8;

    float acc[2][8][4];
#pragma unroll
    for (int mi = 0; mi < 2; mi++)
#pragma unroll
        for (int ni = 0; ni < 8; ni++)
#pragma unroll
            for (int q = 0; q < 4; q++) acc[mi][ni][q] = 0.f;

    // ---- copy-thread indices ----
    int aRow  = tid >> 1;              // A row (0..127)
    int aHalf = (tid & 1) * 16;        // k offset 0 or 16 (bf16 units)
    int bRow  = tid >> 3;              // B k row (0..31)
    int bCol  = (tid & 7) * 16;        // B n offset (bf16 units), 16 per thread

    int tokA = (MODE == 0) ? sTok[aRow] : -1;
    bool aValid = (MODE == 0) ? (tokA >= 0) : ((rowBase + aRow) < count);
    const __nv_bfloat16 *aHiP, *aLoP;
    if (MODE == 0) {
        size_t ao = (size_t)(tokA < 0 ? 0 : tokA) * DMODEL;
        aHiP = g_xHi + ao; aLoP = g_xLo + ao;
    } else {
        size_t ao = ((size_t)e * CAP + rowBase + aRow) * (size_t)DHID;
        aHiP = g_hHi + ao; aLoP = g_hLo + ao;
    }
    // B global: [e][k][n] plane, this thread covers row (k0+bRow), cols bCol..bCol+15
    const __nv_bfloat16* bHiP = ((MODE == 0) ? g_w1Hi : g_w2Hi)
        + (size_t)e * Ktot * Ntot + (size_t)bRow * Ntot + colBase + bCol;
    const __nv_bfloat16* bLoP = ((MODE == 0) ? g_w1Lo : g_w2Lo)
        + (size_t)e * Ktot * Ntot + (size_t)bRow * Ntot + colBase + bCol;

    const uint4 zero4 = make_uint4(0u, 0u, 0u, 0u);
    uint4 aRegH[2], aRegL[2], bRegH[2], bRegL[2];

    // prefetch k0 = 0
#pragma unroll
    for (int j = 0; j < 2; j++) {
        aRegH[j] = aValid ? *(const uint4*)(aHiP + aHalf + 8 * j) : zero4;
        aRegL[j] = aValid ? *(const uint4*)(aLoP + aHalf + 8 * j) : zero4;
        bRegH[j] = *(const uint4*)(bHiP + 8 * j);
        bRegL[j] = *(const uint4*)(bLoP + 8 * j);
    }

    for (int k0 = 0; k0 < Ktot; k0 += BK) {
        __syncthreads();   // previous stage fully consumed

        // ---- store regs -> SMEM ----
#pragma unroll
        for (int j = 0; j < 2; j++) {
            int ai = aRow * A_STRIDE + aHalf + 8 * j;
            *(uint4*)&AsHi[ai] = aRegH[j];
            *(uint4*)&AsLo[ai] = aRegL[j];
            uint32_t off = bswz(bRow, (bCol + 8 * j) * 2);
            *(uint4*)((char*)BsHi + off) = bRegH[j];
            *(uint4*)((char*)BsLo + off) = bRegL[j];
        }
        __syncthreads();

        // ---- prefetch next stage (overlaps compute) ----
        if (k0 + BK < Ktot) {
            int kn = k0 + BK;
#pragma unroll
            for (int j = 0; j < 2; j++) {
                aRegH[j] = aValid ? *(const uint4*)(aHiP + kn + aHalf + 8 * j) : zero4;
                aRegL[j] = aValid ? *(const uint4*)(aLoP + kn + aHalf + 8 * j) : zero4;
                bRegH[j] = *(const uint4*)(bHiP + (size_t)kn * Ntot + 8 * j);
                bRegL[j] = *(const uint4*)(bLoP + (size_t)kn * Ntot + 8 * j);
            }
        }

        // ---- compute: 2 k16 steps (Round-3-validated fragment paths) ----
#pragma unroll
        for (int s = 0; s < 2; s++) {
            int kk = s * 16;
            uint32_t aHi[2][4], aLo[2][4];
#pragma unroll
            for (int mi = 0; mi < 2; mi++) {
                int r0 = (warpM * 32 + mi * 16 + gid) * A_STRIDE + kk + 2 * tig;
                int r1 = r0 + 8 * A_STRIDE;
                aHi[mi][0] = *(const uint32_t*)&AsHi[r0];
                aHi[mi][1] = *(const uint32_t*)&AsHi[r1];
                aHi[mi][2] = *(const uint32_t*)&AsHi[r0 + 8];
                aHi[mi][3] = *(const uint32_t*)&AsHi[r1 + 8];
                aLo[mi][0] = *(const uint32_t*)&AsLo[r0];
                aLo[mi][1] = *(const uint32_t*)&AsLo[r1];
                aLo[mi][2] = *(const uint32_t*)&AsLo[r0 + 8];
                aLo[mi][3] = *(const uint32_t*)&AsLo[r1 + 8];
            }
#pragma unroll
            for (int u = 0; u < 4; u++) {
                int n0 = warpN * 64 + u * 16;
                uint32_t off = bswz(kk + lm_kd, (n0 + lm_nd) * 2);
                uint32_t bh[4], bl[4];
                ldsm_x4_t(bh[0], bh[1], bh[2], bh[3], bHiBase + off);
                ldsm_x4_t(bl[0], bl[1], bl[2], bl[3], bLoBase + off);
#pragma unroll
                for (int v = 0; v < 2; v++) {
                    int ni = u * 2 + v;
                    uint32_t bhp[2] = { bh[v * 2 + 0], bh[v * 2 + 1] };
                    uint32_t blp[2] = { bl[v * 2 + 0], bl[v * 2 + 1] };
#pragma unroll
                    for (int mi = 0; mi < 2; mi++) {
                        mma_bf16(acc[mi][ni], aHi[mi], bhp);
                        mma_bf16(acc[mi][ni], aLo[mi], bhp);
                        mma_bf16(acc[mi][ni], aHi[mi], blp);
                    }
                }
            }
        }
    }

    // ---- epilogue ----
#pragma unroll
    for (int mi = 0; mi < 2; mi++) {
#pragma unroll
        for (int rsel = 0; rsel < 2; rsel++) {
            int rloc = warpM * 32 + mi * 16 + gid + rsel * 8;
            int tok = sTok[rloc];
            if (tok < 0) continue;
#pragma unroll
            for (int ni = 0; ni < 8; ni++) {
                int cloc = warpN * 64 + ni * 8 + tig * 2;
                float2 bv = *(const float2*)(bias + cloc);
                float v0 = acc[mi][ni][rsel * 2 + 0] + bv.x;
                float v1 = acc[mi][ni][rsel * 2 + 1] + bv.y;
                if (MODE == 0) {
                    v0 = v0 > 0.f ? v0 : 0.f;
                    v1 = v1 > 0.f ? v1 : 0.f;
                    __nv_bfloat16 h0 = __float2bfloat16(v0);
                    __nv_bfloat16 h1 = __float2bfloat16(v1);
                    __nv_bfloat162 H = {h0, h1};
                    __nv_bfloat162 L = {__float2bfloat16(v0 - __bfloat162float(h0)),
                                        __float2bfloat16(v1 - __bfloat162float(h1))};
                    size_t o = ((size_t)e * CAP + rowBase + rloc) * DHID + colBase + cloc;
                    *(uint32_t*)(g_hHi + o) = *(uint32_t*)&H;
                    *(uint32_t*)(g_hLo + o) = *(uint32_t*)&L;
                } else {
                    float* op = outg + (size_t)tok * DMODEL + colBase + cloc;
                    *(float2*)op = make_float2(v0, v1);
                }
            }
        }
    }
}

// ---------------- launch ----------------------------------------------------
extern "C" void kernel_launch(void* const* d_in, const int* in_sizes, int n_in,
                              void* d_out, int out_size) {
    const float* x  = (const float*)d_in[0];
    const float* Wg = (const float*)d_in[1];
    const float* bg = (const float*)d_in[2];
    const float* W1 = (const float*)d_in[3];
    const float* b1 = (const float*)d_in[4];
    const float* W2 = (const float*)d_in[5];
    const float* b2 = (const float*)d_in[6];
    float* out = (float*)d_out;

    cudaMemsetAsync(d_out, 0, (size_t)out_size * sizeof(float));

    moe_router<<<NTOK / 8, 256>>>(x, Wg, bg);
    moe_scan<<<1, 256>>>();
    convert_plane<<<(NTOK * DMODEL) / 1024, 256>>>(x, 0);
    convert_plane<<<(NEXP * DMODEL * DHID) / 1024, 256>>>(W1, 1);
    convert_plane<<<(NEXP * DHID * DMODEL) / 1024, 256>>>(W2, 2);

    moe_ffn<0><<<dim3(DHID / BN, CAP / BM, NEXP), 256>>>(b1, nullptr);
    moe_ffn<1><<<dim3(DMODEL / BN, CAP / BM, NEXP), 256>>>(b2, out);
}

// round 8
// speedup vs baseline: 1.0774x; 1.0774x over previous
#include <cuda_runtime.h>
#include <cuda_bf16.h>
#include <cstdint>

// Problem constants (fixed by the reference)
#define NTOK   8192
#define DMODEL 1024
#define DHID   4096
#define NEXP   8
#define CAP    2048

// ---------------- scratch (allocation-free: __device__ globals) ------------
__device__ int   g_route[NTOK];
__device__ int   g_toklist[NEXP * CAP];
__device__ int   g_count[NEXP];

// bf16 hi/lo planes (same layouts as the fp32 originals; NO transposes)
__device__ __align__(16) __nv_bfloat16 g_xHi[(size_t)NTOK * DMODEL];
__device__ __align__(16) __nv_bfloat16 g_xLo[(size_t)NTOK * DMODEL];
__device__ __align__(16) __nv_bfloat16 g_w1Hi[(size_t)NEXP * DMODEL * DHID]; // [e][k][n]
__device__ __align__(16) __nv_bfloat16 g_w1Lo[(size_t)NEXP * DMODEL * DHID];
__device__ __align__(16) __nv_bfloat16 g_w2Hi[(size_t)NEXP * DHID * DMODEL]; // [e][k][n]
__device__ __align__(16) __nv_bfloat16 g_w2Lo[(size_t)NEXP * DHID * DMODEL];
__device__ __align__(16) __nv_bfloat16 g_hHi[(size_t)NEXP * CAP * DHID];     // [e][row][k]
__device__ __align__(16) __nv_bfloat16 g_hLo[(size_t)NEXP * CAP * DHID];

// ---------------- PTX helpers ----------------------------------------------
__device__ __forceinline__ uint32_t smem_u32(const void* p) {
    return (uint32_t)__cvta_generic_to_shared(p);
}

__device__ __forceinline__ void mma_bf16(float* c, const uint32_t* a, const uint32_t* b) {
    asm volatile(
        "mma.sync.aligned.m16n8k16.row.col.f32.bf16.bf16.f32 "
        "{%0,%1,%2,%3}, {%4,%5,%6,%7}, {%8,%9}, {%0,%1,%2,%3};"
        : "+f"(c[0]), "+f"(c[1]), "+f"(c[2]), "+f"(c[3])
        : "r"(a[0]), "r"(a[1]), "r"(a[2]), "r"(a[3]), "r"(b[0]), "r"(b[1]));
}

__device__ __forceinline__ void ldsm_x4_t(uint32_t& r0, uint32_t& r1,
                                          uint32_t& r2, uint32_t& r3, uint32_t addr) {
    asm volatile("ldmatrix.sync.aligned.m8n8.x4.trans.shared.b16 {%0,%1,%2,%3}, [%4];"
        : "=r"(r0), "=r"(r1), "=r"(r2), "=r"(r3) : "r"(addr));
}

// B tile byte offset with XOR swizzle (k row = 256B; spread bits[6:4] by k&7)
__device__ __forceinline__ uint32_t bswz(int k, int nbyte) {
    return (uint32_t)(k * 256 + (nbyte ^ ((k & 7) << 4)));
}

__device__ __forceinline__ void cp_async16(uint32_t dst, const void* src, int srcSize) {
    asm volatile("cp.async.cg.shared.global [%0], [%1], 16, %2;"
        :: "r"(dst), "l"(src), "r"(srcSize) : "memory");
}
#define CP_COMMIT() asm volatile("cp.async.commit_group;" ::: "memory")
#define CP_WAIT1()  asm volatile("cp.async.wait_group 1;" ::: "memory")

// ---------------- router: logits + argmax (top_k = 1) ---------------------
__global__ __launch_bounds__(256) void moe_router(const float* __restrict__ x,
                                                  const float* __restrict__ Wg,
                                                  const float* __restrict__ bg) {
    __shared__ float sWgT[NEXP][DMODEL];
    int tid = threadIdx.x;
    for (int i = tid; i < DMODEL * NEXP; i += 256) {
        int d = i >> 3, e = i & 7;
        sWgT[e][d] = Wg[i];
    }
    __syncthreads();

    int wid = tid >> 5, lane = tid & 31;
    int token = blockIdx.x * 8 + wid;
    const float* xr = x + (size_t)token * DMODEL;

    float acc[NEXP];
#pragma unroll
    for (int e = 0; e < NEXP; e++) acc[e] = 0.f;
    for (int d = lane; d < DMODEL; d += 32) {
        float xv = xr[d];
#pragma unroll
        for (int e = 0; e < NEXP; e++) acc[e] += xv * sWgT[e][d];
    }
#pragma unroll
    for (int e = 0; e < NEXP; e++) {
#pragma unroll
        for (int off = 16; off > 0; off >>= 1)
            acc[e] += __shfl_xor_sync(0xffffffffu, acc[e], off);
    }
    if (lane == 0) {
        int best = 0;
        float bv = acc[0] + bg[0];
#pragma unroll
        for (int e = 1; e < NEXP; e++) {
            float v = acc[e] + bg[e];
            if (v > bv) { bv = v; best = e; }   // first-max tie-break
        }
        g_route[token] = best;
    }
}

// ---------------- ordered capacity scan ------------------------------------
__global__ __launch_bounds__(256) void moe_scan() {
    int tid = threadIdx.x;
    for (int i = tid; i < NEXP * CAP; i += 256) g_toklist[i] = -1;
    __syncthreads();
    int wid = tid >> 5, lane = tid & 31;   // wid == expert id
    int base = 0;
    for (int c = 0; c < NTOK / 32; c++) {
        int token = c * 32 + lane;
        int r = g_route[token];
        unsigned mask = __ballot_sync(0xffffffffu, r == wid);
        if (r == wid) {
            int pos = base + __popc(mask & ((1u << lane) - 1u));
            if (pos < CAP) g_toklist[wid * CAP + pos] = token;
        }
        base += __popc(mask);
    }
    if (lane == 0) g_count[wid] = base < CAP ? base : CAP;
}

// ---------------- fp32 -> bf16 hi/lo (destination chosen DEVICE-SIDE) -------
// __device__ array symbols must never be passed as kernel args from host code
// (host shadow address + GB300 ATS silently writes host memory).
__global__ __launch_bounds__(256) void convert_plane(const float* __restrict__ src,
                                                     int which) {
    __nv_bfloat16 *dHi, *dLo;
    if (which == 0)      { dHi = g_xHi;  dLo = g_xLo;  }
    else if (which == 1) { dHi = g_w1Hi; dLo = g_w1Lo; }
    else                 { dHi = g_w2Hi; dLo = g_w2Lo; }

    size_t i = ((size_t)blockIdx.x * 256 + threadIdx.x) * 4;
    float4 v = *(const float4*)(src + i);
    __nv_bfloat16 h0 = __float2bfloat16(v.x), h1 = __float2bfloat16(v.y);
    __nv_bfloat16 h2 = __float2bfloat16(v.z), h3 = __float2bfloat16(v.w);
    __nv_bfloat16 l0 = __float2bfloat16(v.x - __bfloat162float(h0));
    __nv_bfloat16 l1 = __float2bfloat16(v.y - __bfloat162float(h1));
    __nv_bfloat16 l2 = __float2bfloat16(v.z - __bfloat162float(h2));
    __nv_bfloat16 l3 = __float2bfloat16(v.w - __bfloat162float(h3));
    __nv_bfloat162 H0 = {h0, h1}, H1 = {h2, h3}, L0 = {l0, l1}, L1 = {l2, l3};
    *(uint2*)(dHi + i) = make_uint2(*(uint32_t*)&H0, *(uint32_t*)&H1);
    *(uint2*)(dLo + i) = make_uint2(*(uint32_t*)&L0, *(uint32_t*)&L1);
}

// ---------------- 3xBF16 tensor-core GEMMs + cp.async 3-stage pipeline ------
// Block tile 128x128, BK=32. 8 warps: 4 in M x 2 in N; warp 32x64 via
// 2 m16 x 8 n8 tiles of mma.m16n8k16.bf16, 3 mma per tile (hi*hi+lo*hi+hi*lo).
// Stage SMEM: AHi/ALo (128 rows x 32 bf16, stride 40) + BHi/BLo (32x128 swizzled).

#define BM 128
#define BN 128
#define BK 32
#define A_STRIDE 40                 // bf16 units per A row (80B)
#define A_PLANE  (BM * A_STRIDE * 2)   // 10240 B
#define B_PLANE  (BK * 256)            // 8192 B
#define STAGE_B  (2 * A_PLANE + 2 * B_PLANE)  // 36864 B
#define NSTAGE   3
#define FFN_SMEM (NSTAGE * STAGE_B)    // 110592 B

template <int MODE>
__global__ __launch_bounds__(256, 1) void moe_ffn(const float* __restrict__ bias_g,
                                                  float* __restrict__ outg) {
    const int Ktot = (MODE == 0) ? DMODEL : DHID;
    const int Ntot = (MODE == 0) ? DHID : DMODEL;

    int e = blockIdx.z;
    int count = g_count[e];
    int rowBase = blockIdx.y * BM;
    if (rowBase >= count) return;
    int colBase = blockIdx.x * BN;

    extern __shared__ __align__(16) char dyn[];
    __shared__ int sTok[BM];

    int tid = threadIdx.x;
    for (int i = tid; i < BM; i += 256) {
        int row = rowBase + i;
        sTok[i] = (row < count) ? g_toklist[e * CAP + row] : -1;
    }
    __syncthreads();

    const float* bias = bias_g + (size_t)e * Ntot + colBase;
    uint32_t smBase = smem_u32(dyn);

    int warpId = tid >> 5, lane = tid & 31;
    int warpM = warpId & 3;            // M offset *32
    int warpN = warpId >> 2;           // N offset *64
    int gid = lane >> 2, tig = lane & 3;

    int lm_m  = lane >> 3;
    int lm_rr = lane & 7;
    int lm_kd = (lm_m & 1) * 8 + lm_rr;
    int lm_nd = (lm_m >> 1) * 8;

    float acc[2][8][4];
#pragma unroll
    for (int mi = 0; mi < 2; mi++)
#pragma unroll
        for (int ni = 0; ni < 8; ni++)
#pragma unroll
            for (int q = 0; q < 4; q++) acc[mi][ni][q] = 0.f;

    // ---- copy-thread indices (identical coverage to R7) ----
    int aRow  = tid >> 1;              // A row (0..127)
    int aK16  = (tid & 1) * 16;        // k offset 0 or 16 (bf16 units)
    int bRow  = tid >> 3;              // B k row (0..31)
    int bCol  = (tid & 7) * 16;        // B n offset (bf16 units)

    int tokA = (MODE == 0) ? sTok[aRow] : -1;
    bool aValid = (MODE == 0) ? (tokA >= 0) : ((rowBase + aRow) < count);
    int aSize = aValid ? 16 : 0;
    const __nv_bfloat16 *aHiP, *aLoP;
    if (MODE == 0) {
        size_t ao = (size_t)(tokA < 0 ? 0 : tokA) * DMODEL;
        aHiP = g_xHi + ao; aLoP = g_xLo + ao;
    } else {
        size_t ao = ((size_t)e * CAP + rowBase + aRow) * (size_t)DHID;
        aHiP = g_hHi + ao; aLoP = g_hLo + ao;
    }
    const __nv_bfloat16* bHiP = ((MODE == 0) ? g_w1Hi : g_w2Hi)
        + (size_t)e * Ktot * Ntot + (size_t)bRow * Ntot + colBase + bCol;
    const __nv_bfloat16* bLoP = ((MODE == 0) ? g_w1Lo : g_w2Lo)
        + (size_t)e * Ktot * Ntot + (size_t)bRow * Ntot + colBase + bCol;

    uint32_t aDst = (uint32_t)aRow * (A_STRIDE * 2) + (uint32_t)aK16 * 2;  // bytes
    const int nIter = Ktot / BK;

    // ---- issue one stage of async copies ----
    auto issue_stage = [&](int i) {
        uint32_t base = smBase + (uint32_t)(i % NSTAGE) * STAGE_B;
        uint32_t pAHi = base, pALo = base + A_PLANE;
        uint32_t pBHi = base + 2 * A_PLANE, pBLo = base + 2 * A_PLANE + B_PLANE;
        int k0 = i * BK;
        size_t bK = (size_t)k0 * Ntot;
#pragma unroll
        for (int j = 0; j < 2; j++) {
            uint32_t ad = aDst + j * 16u;
            cp_async16(pAHi + ad, aHiP + k0 + aK16 + j * 8, aSize);
            cp_async16(pALo + ad, aLoP + k0 + aK16 + j * 8, aSize);
            uint32_t bd = bswz(bRow, bCol * 2 + j * 16);
            cp_async16(pBHi + bd, bHiP + bK + j * 8, 16);
            cp_async16(pBLo + bd, bLoP + bK + j * 8, 16);
        }
    };

    issue_stage(0); CP_COMMIT();
    issue_stage(1); CP_COMMIT();

    for (int i = 0; i < nIter; i++) {
        CP_WAIT1();            // stage i landed
        __syncthreads();       // stage (i+2)%3 buffer free (readers of i-1 done)
        if (i + 2 < nIter) issue_stage(i + 2);
        CP_COMMIT();

        uint32_t base = smBase + (uint32_t)(i % NSTAGE) * STAGE_B;
        const __nv_bfloat16* AsHi = (const __nv_bfloat16*)(dyn + (i % NSTAGE) * STAGE_B);
        const __nv_bfloat16* AsLo = (const __nv_bfloat16*)(dyn + (i % NSTAGE) * STAGE_B + A_PLANE);
        uint32_t pBHi = base + 2 * A_PLANE, pBLo = base + 2 * A_PLANE + B_PLANE;

#pragma unroll
        for (int s = 0; s < 2; s++) {
            int kk = s * 16;
            uint32_t aHi[2][4], aLo[2][4];
#pragma unroll
            for (int mi = 0; mi < 2; mi++) {
                int r0 = (warpM * 32 + mi * 16 + gid) * A_STRIDE + kk + 2 * tig;
                int r1 = r0 + 8 * A_STRIDE;
                aHi[mi][0] = *(const uint32_t*)&AsHi[r0];
                aHi[mi][1] = *(const uint32_t*)&AsHi[r1];
                aHi[mi][2] = *(const uint32_t*)&AsHi[r0 + 8];
                aHi[mi][3] = *(const uint32_t*)&AsHi[r1 + 8];
                aLo[mi][0] = *(const uint32_t*)&AsLo[r0];
                aLo[mi][1] = *(const uint32_t*)&AsLo[r1];
                aLo[mi][2] = *(const uint32_t*)&AsLo[r0 + 8];
                aLo[mi][3] = *(const uint32_t*)&AsLo[r1 + 8];
            }
#pragma unroll
            for (int u = 0; u < 4; u++) {
                int n0 = warpN * 64 + u * 16;
                uint32_t off = bswz(kk + lm_kd, (n0 + lm_nd) * 2);
                uint32_t bh[4], bl[4];
                ldsm_x4_t(bh[0], bh[1], bh[2], bh[3], pBHi + off);
                ldsm_x4_t(bl[0], bl[1], bl[2], bl[3], pBLo + off);
#pragma unroll
                for (int v = 0; v < 2; v++) {
                    int ni = u * 2 + v;
                    uint32_t bhp[2] = { bh[v * 2 + 0], bh[v * 2 + 1] };
                    uint32_t blp[2] = { bl[v * 2 + 0], bl[v * 2 + 1] };
#pragma unroll
                    for (int mi = 0; mi < 2; mi++) {
                        mma_bf16(acc[mi][ni], aHi[mi], bhp);
                        mma_bf16(acc[mi][ni], aLo[mi], bhp);
                        mma_bf16(acc[mi][ni], aHi[mi], blp);
                    }
                }
            }
        }
        __syncthreads();       // all reads of stage i done before it is rewritten
    }

    // ---- epilogue ----
#pragma unroll
    for (int mi = 0; mi < 2; mi++) {
#pragma unroll
        for (int rsel = 0; rsel < 2; rsel++) {
            int rloc = warpM * 32 + mi * 16 + gid + rsel * 8;
            int tok = sTok[rloc];
            if (tok < 0) continue;
#pragma unroll
            for (int ni = 0; ni < 8; ni++) {
                int cloc = warpN * 64 + ni * 8 + tig * 2;
                float2 bv = *(const float2*)(bias + cloc);
                float v0 = acc[mi][ni][rsel * 2 + 0] + bv.x;
                float v1 = acc[mi][ni][rsel * 2 + 1] + bv.y;
                if (MODE == 0) {
                    v0 = v0 > 0.f ? v0 : 0.f;
                    v1 = v1 > 0.f ? v1 : 0.f;
                    __nv_bfloat16 h0 = __float2bfloat16(v0);
                    __nv_bfloat16 h1 = __float2bfloat16(v1);
                    __nv_bfloat162 H = {h0, h1};
                    __nv_bfloat162 L = {__float2bfloat16(v0 - __bfloat162float(h0)),
                                        __float2bfloat16(v1 - __bfloat162float(h1))};
                    size_t o = ((size_t)e * CAP + rowBase + rloc) * DHID + colBase + cloc;
                    *(uint32_t*)(g_hHi + o) = *(uint32_t*)&H;
                    *(uint32_t*)(g_hLo + o) = *(uint32_t*)&L;
                } else {
                    float* op = outg + (size_t)tok * DMODEL + colBase + cloc;
                    *(float2*)op = make_float2(v0, v1);
                }
            }
        }
    }
}

// ---------------- launch ----------------------------------------------------
extern "C" void kernel_launch(void* const* d_in, const int* in_sizes, int n_in,
                              void* d_out, int out_size) {
    const float* x  = (const float*)d_in[0];
    const float* Wg = (const float*)d_in[1];
    const float* bg = (const float*)d_in[2];
    const float* W1 = (const float*)d_in[3];
    const float* b1 = (const float*)d_in[4];
    const float* W2 = (const float*)d_in[5];
    const float* b2 = (const float*)d_in[6];
    float* out = (float*)d_out;

    cudaFuncSetAttribute(moe_ffn<0>, cudaFuncAttributeMaxDynamicSharedMemorySize, FFN_SMEM);
    cudaFuncSetAttribute(moe_ffn<1>, cudaFuncAttributeMaxDynamicSharedMemorySize, FFN_SMEM);

    cudaMemsetAsync(d_out, 0, (size_t)out_size * sizeof(float));

    moe_router<<<NTOK / 8, 256>>>(x, Wg, bg);
    moe_scan<<<1, 256>>>();
    convert_plane<<<(NTOK * DMODEL) / 1024, 256>>>(x, 0);
    convert_plane<<<(NEXP * DMODEL * DHID) / 1024, 256>>>(W1, 1);
    convert_plane<<<(NEXP * DHID * DMODEL) / 1024, 256>>>(W2, 2);

    moe_ffn<0><<<dim3(DHID / BN, CAP / BM, NEXP), 256, FFN_SMEM>>>(b1, nullptr);
    moe_ffn<1><<<dim3(DMODEL / BN, CAP / BM, NEXP), 256, FFN_SMEM>>>(b2, out);
}

// round 9
// speedup vs baseline: 1.1032x; 1.0240x over previous
#include <cuda_runtime.h>
#include <cuda_bf16.h>
#include <cstdint>

// Problem constants (fixed by the reference)
#define NTOK   8192
#define DMODEL 1024
#define DHID   4096
#define NEXP   8
#define CAP    2048

// ---------------- scratch (allocation-free: __device__ globals) ------------
__device__ int   g_route[NTOK];
__device__ int   g_toklist[NEXP * CAP];
__device__ int   g_count[NEXP];

// bf16 hi/lo planes (same layouts as the fp32 originals; NO transposes)
__device__ __align__(16) __nv_bfloat16 g_xHi[(size_t)NTOK * DMODEL];
__device__ __align__(16) __nv_bfloat16 g_xLo[(size_t)NTOK * DMODEL];
__device__ __align__(16) __nv_bfloat16 g_w1Hi[(size_t)NEXP * DMODEL * DHID]; // [e][k][n]
__device__ __align__(16) __nv_bfloat16 g_w1Lo[(size_t)NEXP * DMODEL * DHID];
__device__ __align__(16) __nv_bfloat16 g_w2Hi[(size_t)NEXP * DHID * DMODEL]; // [e][k][n]
__device__ __align__(16) __nv_bfloat16 g_w2Lo[(size_t)NEXP * DHID * DMODEL];
__device__ __align__(16) __nv_bfloat16 g_hHi[(size_t)NEXP * CAP * DHID];     // [e][row][k]
__device__ __align__(16) __nv_bfloat16 g_hLo[(size_t)NEXP * CAP * DHID];

// ---------------- PTX helpers ----------------------------------------------
__device__ __forceinline__ uint32_t smem_u32(const void* p) {
    return (uint32_t)__cvta_generic_to_shared(p);
}

__device__ __forceinline__ void mma_bf16(float* c, const uint32_t* a, const uint32_t* b) {
    asm volatile(
        "mma.sync.aligned.m16n8k16.row.col.f32.bf16.bf16.f32 "
        "{%0,%1,%2,%3}, {%4,%5,%6,%7}, {%8,%9}, {%0,%1,%2,%3};"
        : "+f"(c[0]), "+f"(c[1]), "+f"(c[2]), "+f"(c[3])
        : "r"(a[0]), "r"(a[1]), "r"(a[2]), "r"(a[3]), "r"(b[0]), "r"(b[1]));
}

__device__ __forceinline__ void ldsm_x4_t(uint32_t& r0, uint32_t& r1,
                                          uint32_t& r2, uint32_t& r3, uint32_t addr) {
    asm volatile("ldmatrix.sync.aligned.m8n8.x4.trans.shared.b16 {%0,%1,%2,%3}, [%4];"
        : "=r"(r0), "=r"(r1), "=r"(r2), "=r"(r3) : "r"(addr));
}

// B tile byte offset with XOR swizzle (k row = 256B; spread bits[6:4] by k&7)
__device__ __forceinline__ uint32_t bswz(int k, int nbyte) {
    return (uint32_t)(k * 256 + (nbyte ^ ((k & 7) << 4)));
}

__device__ __forceinline__ void cp_async16(uint32_t dst, const void* src, int srcSize) {
    asm volatile("cp.async.cg.shared.global [%0], [%1], 16, %2;"
        :: "r"(dst), "l"(src), "r"(srcSize) : "memory");
}
#define CP_COMMIT() asm volatile("cp.async.commit_group;" ::: "memory")
#define CP_WAIT1()  asm volatile("cp.async.wait_group 1;" ::: "memory")

// ---------------- router: logits + argmax (top_k = 1) ---------------------
__global__ __launch_bounds__(256) void moe_router(const float* __restrict__ x,
                                                  const float* __restrict__ Wg,
                                                  const float* __restrict__ bg) {
    __shared__ float sWgT[NEXP][DMODEL];
    int tid = threadIdx.x;
    for (int i = tid; i < DMODEL * NEXP; i += 256) {
        int d = i >> 3, e = i & 7;
        sWgT[e][d] = Wg[i];
    }
    __syncthreads();

    int wid = tid >> 5, lane = tid & 31;
    int token = blockIdx.x * 8 + wid;
    const float* xr = x + (size_t)token * DMODEL;

    float acc[NEXP];
#pragma unroll
    for (int e = 0; e < NEXP; e++) acc[e] = 0.f;
    for (int d = lane; d < DMODEL; d += 32) {
        float xv = xr[d];
#pragma unroll
        for (int e = 0; e < NEXP; e++) acc[e] += xv * sWgT[e][d];
    }
#pragma unroll
    for (int e = 0; e < NEXP; e++) {
#pragma unroll
        for (int off = 16; off > 0; off >>= 1)
            acc[e] += __shfl_xor_sync(0xffffffffu, acc[e], off);
    }
    if (lane == 0) {
        int best = 0;
        float bv = acc[0] + bg[0];
#pragma unroll
        for (int e = 1; e < NEXP; e++) {
            float v = acc[e] + bg[e];
            if (v > bv) { bv = v; best = e; }   // first-max tie-break
        }
        g_route[token] = best;
    }
}

// ---------------- ordered capacity scan ------------------------------------
__global__ __launch_bounds__(256) void moe_scan() {
    int tid = threadIdx.x;
    for (int i = tid; i < NEXP * CAP; i += 256) g_toklist[i] = -1;
    __syncthreads();
    int wid = tid >> 5, lane = tid & 31;   // wid == expert id
    int base = 0;
    for (int c = 0; c < NTOK / 32; c++) {
        int token = c * 32 + lane;
        int r = g_route[token];
        unsigned mask = __ballot_sync(0xffffffffu, r == wid);
        if (r == wid) {
            int pos = base + __popc(mask & ((1u << lane) - 1u));
            if (pos < CAP) g_toklist[wid * CAP + pos] = token;
        }
        base += __popc(mask);
    }
    if (lane == 0) g_count[wid] = base < CAP ? base : CAP;
}

// ---------------- fp32 -> bf16 hi/lo (destination chosen DEVICE-SIDE) -------
// __device__ array symbols must never be passed as kernel args from host code
// (host shadow address + GB300 ATS silently writes host memory).
__global__ __launch_bounds__(256) void convert_plane(const float* __restrict__ src,
                                                     int which) {
    __nv_bfloat16 *dHi, *dLo;
    if (which == 0)      { dHi = g_xHi;  dLo = g_xLo;  }
    else if (which == 1) { dHi = g_w1Hi; dLo = g_w1Lo; }
    else                 { dHi = g_w2Hi; dLo = g_w2Lo; }

    size_t i = ((size_t)blockIdx.x * 256 + threadIdx.x) * 4;
    float4 v = *(const float4*)(src + i);
    __nv_bfloat16 h0 = __float2bfloat16(v.x), h1 = __float2bfloat16(v.y);
    __nv_bfloat16 h2 = __float2bfloat16(v.z), h3 = __float2bfloat16(v.w);
    __nv_bfloat16 l0 = __float2bfloat16(v.x - __bfloat162float(h0));
    __nv_bfloat16 l1 = __float2bfloat16(v.y - __bfloat162float(h1));
    __nv_bfloat16 l2 = __float2bfloat16(v.z - __bfloat162float(h2));
    __nv_bfloat16 l3 = __float2bfloat16(v.w - __bfloat162float(h3));
    __nv_bfloat162 H0 = {h0, h1}, H1 = {h2, h3}, L0 = {l0, l1}, L1 = {l2, l3};
    *(uint2*)(dHi + i) = make_uint2(*(uint32_t*)&H0, *(uint32_t*)&H1);
    *(uint2*)(dLo + i) = make_uint2(*(uint32_t*)&L0, *(uint32_t*)&L1);
}

// ---------------- 3xBF16 tensor-core GEMMs, 512 threads ---------------------
// Block tile 128x128, BK=32, cp.async 3-stage pipeline.
// 16 warps in a 4(M) x 4(N) grid; each warp computes 32x32 via 2 m16 x 4 n8
// tiles. 3-term bf16 emulation issued TERM-MAJOR (hi*hi pass, lo*hi pass,
// hi*lo pass) so consecutive MMAs never share an accumulator (no RAW chain).

#define BM 128
#define BN 128
#define BK 32
#define A_STRIDE 40                 // bf16 units per A row (80B)
#define A_PLANE  (BM * A_STRIDE * 2)   // 10240 B
#define B_PLANE  (BK * 256)            // 8192 B
#define STAGE_B  (2 * A_PLANE + 2 * B_PLANE)  // 36864 B
#define NSTAGE   3
#define FFN_SMEM (NSTAGE * STAGE_B)    // 110592 B

template <int MODE>
__global__ __launch_bounds__(512, 1) void moe_ffn(const float* __restrict__ bias_g,
                                                  float* __restrict__ outg) {
    const int Ktot = (MODE == 0) ? DMODEL : DHID;
    const int Ntot = (MODE == 0) ? DHID : DMODEL;

    int e = blockIdx.z;
    int count = g_count[e];
    int rowBase = blockIdx.y * BM;
    if (rowBase >= count) return;
    int colBase = blockIdx.x * BN;

    extern __shared__ __align__(16) char dyn[];
    __shared__ int sTok[BM];

    int tid = threadIdx.x;
    if (tid < BM) {
        int row = rowBase + tid;
        sTok[tid] = (row < count) ? g_toklist[e * CAP + row] : -1;
    }
    __syncthreads();

    const float* bias = bias_g + (size_t)e * Ntot + colBase;
    uint32_t smBase = smem_u32(dyn);

    int warpId = tid >> 5, lane = tid & 31;
    int warpM = warpId & 3;            // M offset *32
    int warpN = warpId >> 2;           // N offset *32
    int gid = lane >> 2, tig = lane & 3;

    int lm_m  = lane >> 3;
    int lm_rr = lane & 7;
    int lm_kd = (lm_m & 1) * 8 + lm_rr;
    int lm_nd = (lm_m >> 1) * 8;

    float acc[2][4][4];
#pragma unroll
    for (int mi = 0; mi < 2; mi++)
#pragma unroll
        for (int ni = 0; ni < 4; ni++)
#pragma unroll
            for (int q = 0; q < 4; q++) acc[mi][ni][q] = 0.f;

    // ---- copy-thread indices (512 threads, 4 cp.async each per stage) ----
    int aRow  = tid >> 2;              // A row (0..127), 4 threads/row
    int aSeg  = (tid & 3) * 8;         // k offset 0,8,16,24 (bf16 units)
    int bRow  = tid >> 4;              // B k row (0..31), 16 threads/row
    int bCol  = (tid & 15) * 8;        // B n offset (bf16 units)

    int tokA = (MODE == 0) ? sTok[aRow] : -1;
    bool aValid = (MODE == 0) ? (tokA >= 0) : ((rowBase + aRow) < count);
    int aSize = aValid ? 16 : 0;
    const __nv_bfloat16 *aHiP, *aLoP;
    if (MODE == 0) {
        size_t ao = (size_t)(tokA < 0 ? 0 : tokA) * DMODEL;
        aHiP = g_xHi + ao; aLoP = g_xLo + ao;
    } else {
        size_t ao = ((size_t)e * CAP + rowBase + aRow) * (size_t)DHID;
        aHiP = g_hHi + ao; aLoP = g_hLo + ao;
    }
    const __nv_bfloat16* bHiP = ((MODE == 0) ? g_w1Hi : g_w2Hi)
        + (size_t)e * Ktot * Ntot + (size_t)bRow * Ntot + colBase + bCol;
    const __nv_bfloat16* bLoP = ((MODE == 0) ? g_w1Lo : g_w2Lo)
        + (size_t)e * Ktot * Ntot + (size_t)bRow * Ntot + colBase + bCol;

    uint32_t aDst = (uint32_t)aRow * (A_STRIDE * 2) + (uint32_t)aSeg * 2;  // bytes
    uint32_t bDst = bswz(bRow, bCol * 2);
    const int nIter = Ktot / BK;

    auto issue_stage = [&](int i) {
        uint32_t base = smBase + (uint32_t)(i % NSTAGE) * STAGE_B;
        int k0 = i * BK;
        size_t bK = (size_t)k0 * Ntot;
        cp_async16(base + aDst,                       aHiP + k0 + aSeg, aSize);
        cp_async16(base + A_PLANE + aDst,             aLoP + k0 + aSeg, aSize);
        cp_async16(base + 2 * A_PLANE + bDst,         bHiP + bK, 16);
        cp_async16(base + 2 * A_PLANE + B_PLANE + bDst, bLoP + bK, 16);
    };

    issue_stage(0); CP_COMMIT();
    issue_stage(1); CP_COMMIT();

    for (int i = 0; i < nIter; i++) {
        CP_WAIT1();            // stage i landed
        __syncthreads();
        if (i + 2 < nIter) issue_stage(i + 2);
        CP_COMMIT();

        uint32_t base = smBase + (uint32_t)(i % NSTAGE) * STAGE_B;
        const __nv_bfloat16* AsHi = (const __nv_bfloat16*)(dyn + (i % NSTAGE) * STAGE_B);
        const __nv_bfloat16* AsLo = (const __nv_bfloat16*)(dyn + (i % NSTAGE) * STAGE_B + A_PLANE);
        uint32_t pBHi = base + 2 * A_PLANE, pBLo = base + 2 * A_PLANE + B_PLANE;

#pragma unroll
        for (int s = 0; s < 2; s++) {
            int kk = s * 16;
            // ---- A fragments (R3-validated direct-LDS path) ----
            uint32_t aHi[2][4], aLo[2][4];
#pragma unroll
            for (int mi = 0; mi < 2; mi++) {
                int r0 = (warpM * 32 + mi * 16 + gid) * A_STRIDE + kk + 2 * tig;
                int r1 = r0 + 8 * A_STRIDE;
                aHi[mi][0] = *(const uint32_t*)&AsHi[r0];
                aHi[mi][1] = *(const uint32_t*)&AsHi[r1];
                aHi[mi][2] = *(const uint32_t*)&AsHi[r0 + 8];
                aHi[mi][3] = *(const uint32_t*)&AsHi[r1 + 8];
                aLo[mi][0] = *(const uint32_t*)&AsLo[r0];
                aLo[mi][1] = *(const uint32_t*)&AsLo[r1];
                aLo[mi][2] = *(const uint32_t*)&AsLo[r0 + 8];
                aLo[mi][3] = *(const uint32_t*)&AsLo[r1 + 8];
            }
            // ---- B fragments: warp covers 32 cols = 2 x n16 panels ----
            uint32_t bh[2][4], bl[2][4];
#pragma unroll
            for (int u = 0; u < 2; u++) {
                int n0 = warpN * 32 + u * 16;
                uint32_t off = bswz(kk + lm_kd, (n0 + lm_nd) * 2);
                ldsm_x4_t(bh[u][0], bh[u][1], bh[u][2], bh[u][3], pBHi + off);
                ldsm_x4_t(bl[u][0], bl[u][1], bl[u][2], bl[u][3], pBLo + off);
            }
            // ---- term-major MMA: no consecutive RAW on any accumulator ----
#pragma unroll
            for (int ni = 0; ni < 4; ni++) {           // term 1: hi*hi
                uint32_t bp[2] = { bh[ni >> 1][(ni & 1) * 2], bh[ni >> 1][(ni & 1) * 2 + 1] };
#pragma unroll
                for (int mi = 0; mi < 2; mi++) mma_bf16(acc[mi][ni], aHi[mi], bp);
            }
#pragma unroll
            for (int ni = 0; ni < 4; ni++) {           // term 2: lo*hi
                uint32_t bp[2] = { bh[ni >> 1][(ni & 1) * 2], bh[ni >> 1][(ni & 1) * 2 + 1] };
#pragma unroll
                for (int mi = 0; mi < 2; mi++) mma_bf16(acc[mi][ni], aLo[mi], bp);
            }
#pragma unroll
            for (int ni = 0; ni < 4; ni++) {           // term 3: hi*lo
                uint32_t bp[2] = { bl[ni >> 1][(ni & 1) * 2], bl[ni >> 1][(ni & 1) * 2 + 1] };
#pragma unroll
                for (int mi = 0; mi < 2; mi++) mma_bf16(acc[mi][ni], aHi[mi], bp);
            }
        }
        __syncthreads();       // all reads of stage i done before it is rewritten
    }

    // ---- epilogue ----
#pragma unroll
    for (int mi = 0; mi < 2; mi++) {
#pragma unroll
        for (int rsel = 0; rsel < 2; rsel++) {
            int rloc = warpM * 32 + mi * 16 + gid + rsel * 8;
            int tok = sTok[rloc];
            if (tok < 0) continue;
#pragma unroll
            for (int ni = 0; ni < 4; ni++) {
                int cloc = warpN * 32 + ni * 8 + tig * 2;
                float2 bv = *(const float2*)(bias + cloc);
                float v0 = acc[mi][ni][rsel * 2 + 0] + bv.x;
                float v1 = acc[mi][ni][rsel * 2 + 1] + bv.y;
                if (MODE == 0) {
                    v0 = v0 > 0.f ? v0 : 0.f;
                    v1 = v1 > 0.f ? v1 : 0.f;
                    __nv_bfloat16 h0 = __float2bfloat16(v0);
                    __nv_bfloat16 h1 = __float2bfloat16(v1);
                    __nv_bfloat162 H = {h0, h1};
                    __nv_bfloat162 L = {__float2bfloat16(v0 - __bfloat162float(h0)),
                                        __float2bfloat16(v1 - __bfloat162float(h1))};
                    size_t o = ((size_t)e * CAP + rowBase + rloc) * DHID + colBase + cloc;
                    *(uint32_t*)(g_hHi + o) = *(uint32_t*)&H;
                    *(uint32_t*)(g_hLo + o) = *(uint32_t*)&L;
                } else {
                    float* op = outg + (size_t)tok * DMODEL + colBase + cloc;
                    *(float2*)op = make_float2(v0, v1);
                }
            }
        }
    }
}

// ---------------- launch ----------------------------------------------------
extern "C" void kernel_launch(void* const* d_in, const int* in_sizes, int n_in,
                              void* d_out, int out_size) {
    const float* x  = (const float*)d_in[0];
    const float* Wg = (const float*)d_in[1];
    const float* bg = (const float*)d_in[2];
    const float* W1 = (const float*)d_in[3];
    const float* b1 = (const float*)d_in[4];
    const float* W2 = (const float*)d_in[5];
    const float* b2 = (const float*)d_in[6];
    float* out = (float*)d_out;

    cudaFuncSetAttribute(moe_ffn<0>, cudaFuncAttributeMaxDynamicSharedMemorySize, FFN_SMEM);
    cudaFuncSetAttribute(moe_ffn<1>, cudaFuncAttributeMaxDynamicSharedMemorySize, FFN_SMEM);

    cudaMemsetAsync(d_out, 0, (size_t)out_size * sizeof(float));

    moe_router<<<NTOK / 8, 256>>>(x, Wg, bg);
    moe_scan<<<1, 256>>>();
    convert_plane<<<(NTOK * DMODEL) / 1024, 256>>>(x, 0);
    convert_plane<<<(NEXP * DMODEL * DHID) / 1024, 256>>>(W1, 1);
    convert_plane<<<(NEXP * DHID * DMODEL) / 1024, 256>>>(W2, 2);

    moe_ffn<0><<<dim3(DHID / BN, CAP / BM, NEXP), 512, FFN_SMEM>>>(b1, nullptr);
    moe_ffn<1><<<dim3(DMODEL / BN, CAP / BM, NEXP), 512, FFN_SMEM>>>(b2, out);
}

// round 10
// speedup vs baseline: 1.4282x; 1.2945x over previous
#include <cuda_runtime.h>
#include <cuda_fp16.h>
#include <cstdint>

// Problem constants (fixed by the reference)
#define NTOK   8192
#define DMODEL 1024
#define DHID   4096
#define NEXP   8
#define CAP    2048

// ---------------- scratch (allocation-free: __device__ globals) ------------
__device__ int   g_route[NTOK];
__device__ int   g_toklist[NEXP * CAP];
__device__ int   g_count[NEXP];

// fp16 planes: activations split hi+lo (~22 bits), weights single plane (11 bits)
__device__ __align__(16) __half g_xHi[(size_t)NTOK * DMODEL];
__device__ __align__(16) __half g_xLo[(size_t)NTOK * DMODEL];
__device__ __align__(16) __half g_w1H[(size_t)NEXP * DMODEL * DHID];  // [e][k][n]
__device__ __align__(16) __half g_w2H[(size_t)NEXP * DHID * DMODEL];  // [e][k][n]
__device__ __align__(16) __half g_hHi[(size_t)NEXP * CAP * DHID];     // [e][row][k]
__device__ __align__(16) __half g_hLo[(size_t)NEXP * CAP * DHID];

// ---------------- PTX helpers ----------------------------------------------
__device__ __forceinline__ uint32_t smem_u32(const void* p) {
    return (uint32_t)__cvta_generic_to_shared(p);
}

__device__ __forceinline__ void mma_f16(float* c, const uint32_t* a, const uint32_t* b) {
    asm volatile(
        "mma.sync.aligned.m16n8k16.row.col.f32.f16.f16.f32 "
        "{%0,%1,%2,%3}, {%4,%5,%6,%7}, {%8,%9}, {%0,%1,%2,%3};"
        : "+f"(c[0]), "+f"(c[1]), "+f"(c[2]), "+f"(c[3])
        : "r"(a[0]), "r"(a[1]), "r"(a[2]), "r"(a[3]), "r"(b[0]), "r"(b[1]));
}

__device__ __forceinline__ void ldsm_x4_t(uint32_t& r0, uint32_t& r1,
                                          uint32_t& r2, uint32_t& r3, uint32_t addr) {
    asm volatile("ldmatrix.sync.aligned.m8n8.x4.trans.shared.b16 {%0,%1,%2,%3}, [%4];"
        : "=r"(r0), "=r"(r1), "=r"(r2), "=r"(r3) : "r"(addr));
}

// B tile byte offset with XOR swizzle (k row = 256B; spread bits[6:4] by k&7)
__device__ __forceinline__ uint32_t bswz(int k, int nbyte) {
    return (uint32_t)(k * 256 + (nbyte ^ ((k & 7) << 4)));
}

__device__ __forceinline__ void cp_async16(uint32_t dst, const void* src, int srcSize) {
    asm volatile("cp.async.cg.shared.global [%0], [%1], 16, %2;"
        :: "r"(dst), "l"(src), "r"(srcSize) : "memory");
}
#define CP_COMMIT() asm volatile("cp.async.commit_group;" ::: "memory")
#define CP_WAIT1()  asm volatile("cp.async.wait_group 1;" ::: "memory")

// ---------------- router: logits + argmax (top_k = 1) ---------------------
__global__ __launch_bounds__(256) void moe_router(const float* __restrict__ x,
                                                  const float* __restrict__ Wg,
                                                  const float* __restrict__ bg) {
    __shared__ float sWgT[NEXP][DMODEL];
    int tid = threadIdx.x;
    for (int i = tid; i < DMODEL * NEXP; i += 256) {
        int d = i >> 3, e = i & 7;
        sWgT[e][d] = Wg[i];
    }
    __syncthreads();

    int wid = tid >> 5, lane = tid & 31;
    int token = blockIdx.x * 8 + wid;
    const float* xr = x + (size_t)token * DMODEL;

    float acc[NEXP];
#pragma unroll
    for (int e = 0; e < NEXP; e++) acc[e] = 0.f;
    for (int d = lane; d < DMODEL; d += 32) {
        float xv = xr[d];
#pragma unroll
        for (int e = 0; e < NEXP; e++) acc[e] += xv * sWgT[e][d];
    }
#pragma unroll
    for (int e = 0; e < NEXP; e++) {
#pragma unroll
        for (int off = 16; off > 0; off >>= 1)
            acc[e] += __shfl_xor_sync(0xffffffffu, acc[e], off);
    }
    if (lane == 0) {
        int best = 0;
        float bv = acc[0] + bg[0];
#pragma unroll
        for (int e = 1; e < NEXP; e++) {
            float v = acc[e] + bg[e];
            if (v > bv) { bv = v; best = e; }   // first-max tie-break
        }
        g_route[token] = best;
    }
}

// ---------------- ordered capacity scan ------------------------------------
__global__ __launch_bounds__(256) void moe_scan() {
    int tid = threadIdx.x;
    for (int i = tid; i < NEXP * CAP; i += 256) g_toklist[i] = -1;
    __syncthreads();
    int wid = tid >> 5, lane = tid & 31;   // wid == expert id
    int base = 0;
    for (int c = 0; c < NTOK / 32; c++) {
        int token = c * 32 + lane;
        int r = g_route[token];
        unsigned mask = __ballot_sync(0xffffffffu, r == wid);
        if (r == wid) {
            int pos = base + __popc(mask & ((1u << lane) - 1u));
            if (pos < CAP) g_toklist[wid * CAP + pos] = token;
        }
        base += __popc(mask);
    }
    if (lane == 0) g_count[wid] = base < CAP ? base : CAP;
}

// ---------------- fp32 -> fp16 conversions (dest chosen DEVICE-SIDE) --------
// __device__ array symbols must never be passed as kernel args from host code
// (host shadow address + GB300 ATS silently writes host memory).
__global__ __launch_bounds__(256) void convert_x_f16(const float* __restrict__ src) {
    size_t i = ((size_t)blockIdx.x * 256 + threadIdx.x) * 4;
    float4 v = *(const float4*)(src + i);
    __half h0 = __float2half_rn(v.x), h1 = __float2half_rn(v.y);
    __half h2 = __float2half_rn(v.z), h3 = __float2half_rn(v.w);
    __half l0 = __float2half_rn(v.x - __half2float(h0));
    __half l1 = __float2half_rn(v.y - __half2float(h1));
    __half l2 = __float2half_rn(v.z - __half2float(h2));
    __half l3 = __float2half_rn(v.w - __half2float(h3));
    __half2 H0 = {h0, h1}, H1 = {h2, h3}, L0 = {l0, l1}, L1 = {l2, l3};
    *(uint2*)(g_xHi + i) = make_uint2(*(uint32_t*)&H0, *(uint32_t*)&H1);
    *(uint2*)(g_xLo + i) = make_uint2(*(uint32_t*)&L0, *(uint32_t*)&L1);
}

__global__ __launch_bounds__(256) void convert_w_f16(const float* __restrict__ src,
                                                     int which) {
    __half* d = (which == 0) ? g_w1H : g_w2H;
    size_t i = ((size_t)blockIdx.x * 256 + threadIdx.x) * 4;
    float4 v = *(const float4*)(src + i);
    __half2 H0 = {__float2half_rn(v.x), __float2half_rn(v.y)};
    __half2 H1 = {__float2half_rn(v.z), __float2half_rn(v.w)};
    *(uint2*)(d + i) = make_uint2(*(uint32_t*)&H0, *(uint32_t*)&H1);
}

// ---------------- 2-term fp16 tensor-core GEMMs, 512 threads ----------------
// Block tile 128x128, BK=32, cp.async 3-stage pipeline.
// 16 warps in a 4(M) x 4(N) grid; each warp computes 32x32 via 2 m16 x 4 n8
// tiles. 2-term fp16 emulation (aH*bH + aL*bH), term-major issue order.
// A planes: hi+lo (activations, ~22-bit). B plane: single fp16 (weights).

#define BM 128
#define BN 128
#define BK 32
#define A_STRIDE 40                    // fp16 units per A row (80B)
#define A_PLANE  (BM * A_STRIDE * 2)   // 10240 B
#define B_PLANE  (BK * 256)            // 8192 B
#define STAGE_B  (2 * A_PLANE + B_PLANE)  // 28672 B
#define NSTAGE   3
#define FFN_SMEM (NSTAGE * STAGE_B)    // 86016 B

template <int MODE>
__global__ __launch_bounds__(512, 1) void moe_ffn(const float* __restrict__ bias_g,
                                                  float* __restrict__ outg) {
    const int Ktot = (MODE == 0) ? DMODEL : DHID;
    const int Ntot = (MODE == 0) ? DHID : DMODEL;

    int e = blockIdx.z;
    int count = g_count[e];
    int rowBase = blockIdx.y * BM;
    if (rowBase >= count) return;
    int colBase = blockIdx.x * BN;

    extern __shared__ __align__(16) char dyn[];
    __shared__ int sTok[BM];

    int tid = threadIdx.x;
    if (tid < BM) {
        int row = rowBase + tid;
        sTok[tid] = (row < count) ? g_toklist[e * CAP + row] : -1;
    }
    __syncthreads();

    const float* bias = bias_g + (size_t)e * Ntot + colBase;
    uint32_t smBase = smem_u32(dyn);

    int warpId = tid >> 5, lane = tid & 31;
    int warpM = warpId & 3;            // M offset *32
    int warpN = warpId >> 2;           // N offset *32
    int gid = lane >> 2, tig = lane & 3;

    int lm_m  = lane >> 3;
    int lm_rr = lane & 7;
    int lm_kd = (lm_m & 1) * 8 + lm_rr;
    int lm_nd = (lm_m >> 1) * 8;

    float acc[2][4][4];
#pragma unroll
    for (int mi = 0; mi < 2; mi++)
#pragma unroll
        for (int ni = 0; ni < 4; ni++)
#pragma unroll
            for (int q = 0; q < 4; q++) acc[mi][ni][q] = 0.f;

    // ---- copy-thread indices (512 threads, 3 cp.async each per stage) ----
    int aRow  = tid >> 2;              // A row (0..127), 4 threads/row
    int aSeg  = (tid & 3) * 8;         // k offset 0,8,16,24 (fp16 units)
    int bRow  = tid >> 4;              // B k row (0..31), 16 threads/row
    int bCol  = (tid & 15) * 8;        // B n offset (fp16 units)

    int tokA = (MODE == 0) ? sTok[aRow] : -1;
    bool aValid = (MODE == 0) ? (tokA >= 0) : ((rowBase + aRow) < count);
    int aSize = aValid ? 16 : 0;
    const __half *aHiP, *aLoP;
    if (MODE == 0) {
        size_t ao = (size_t)(tokA < 0 ? 0 : tokA) * DMODEL;
        aHiP = g_xHi + ao; aLoP = g_xLo + ao;
    } else {
        size_t ao = ((size_t)e * CAP + rowBase + aRow) * (size_t)DHID;
        aHiP = g_hHi + ao; aLoP = g_hLo + ao;
    }
    const __half* bHP = ((MODE == 0) ? g_w1H : g_w2H)
        + (size_t)e * Ktot * Ntot + (size_t)bRow * Ntot + colBase + bCol;

    uint32_t aDst = (uint32_t)aRow * (A_STRIDE * 2) + (uint32_t)aSeg * 2;  // bytes
    uint32_t bDst = bswz(bRow, bCol * 2);
    const int nIter = Ktot / BK;

    auto issue_stage = [&](int i) {
        uint32_t base = smBase + (uint32_t)(i % NSTAGE) * STAGE_B;
        int k0 = i * BK;
        cp_async16(base + aDst,               aHiP + k0 + aSeg, aSize);
        cp_async16(base + A_PLANE + aDst,     aLoP + k0 + aSeg, aSize);
        cp_async16(base + 2 * A_PLANE + bDst, bHP + (size_t)k0 * Ntot, 16);
    };

    issue_stage(0); CP_COMMIT();
    issue_stage(1); CP_COMMIT();

    for (int i = 0; i < nIter; i++) {
        CP_WAIT1();            // stage i landed
        __syncthreads();
        if (i + 2 < nIter) issue_stage(i + 2);
        CP_COMMIT();

        uint32_t base = smBase + (uint32_t)(i % NSTAGE) * STAGE_B;
        const __half* AsHi = (const __half*)(dyn + (i % NSTAGE) * STAGE_B);
        const __half* AsLo = (const __half*)(dyn + (i % NSTAGE) * STAGE_B + A_PLANE);
        uint32_t pBH = base + 2 * A_PLANE;

#pragma unroll
        for (int s = 0; s < 2; s++) {
            int kk = s * 16;
            // ---- A fragments (validated direct-LDS path) ----
            uint32_t aHi[2][4], aLo[2][4];
#pragma unroll
            for (int mi = 0; mi < 2; mi++) {
                int r0 = (warpM * 32 + mi * 16 + gid) * A_STRIDE + kk + 2 * tig;
                int r1 = r0 + 8 * A_STRIDE;
                aHi[mi][0] = *(const uint32_t*)&AsHi[r0];
                aHi[mi][1] = *(const uint32_t*)&AsHi[r1];
                aHi[mi][2] = *(const uint32_t*)&AsHi[r0 + 8];
                aHi[mi][3] = *(const uint32_t*)&AsHi[r1 + 8];
                aLo[mi][0] = *(const uint32_t*)&AsLo[r0];
                aLo[mi][1] = *(const uint32_t*)&AsLo[r1];
                aLo[mi][2] = *(const uint32_t*)&AsLo[r0 + 8];
                aLo[mi][3] = *(const uint32_t*)&AsLo[r1 + 8];
            }
            // ---- B fragments: warp covers 32 cols = 2 x n16 panels ----
            uint32_t bh[2][4];
#pragma unroll
            for (int u = 0; u < 2; u++) {
                int n0 = warpN * 32 + u * 16;
                uint32_t off = bswz(kk + lm_kd, (n0 + lm_nd) * 2);
                ldsm_x4_t(bh[u][0], bh[u][1], bh[u][2], bh[u][3], pBH + off);
            }
            // ---- term-major MMA: no consecutive RAW on any accumulator ----
#pragma unroll
            for (int ni = 0; ni < 4; ni++) {           // term 1: aH*bH
                uint32_t bp[2] = { bh[ni >> 1][(ni & 1) * 2], bh[ni >> 1][(ni & 1) * 2 + 1] };
#pragma unroll
                for (int mi = 0; mi < 2; mi++) mma_f16(acc[mi][ni], aHi[mi], bp);
            }
#pragma unroll
            for (int ni = 0; ni < 4; ni++) {           // term 2: aL*bH
                uint32_t bp[2] = { bh[ni >> 1][(ni & 1) * 2], bh[ni >> 1][(ni & 1) * 2 + 1] };
#pragma unroll
                for (int mi = 0; mi < 2; mi++) mma_f16(acc[mi][ni], aLo[mi], bp);
            }
        }
        __syncthreads();       // all reads of stage i done before it is rewritten
    }

    // ---- epilogue ----
#pragma unroll
    for (int mi = 0; mi < 2; mi++) {
#pragma unroll
        for (int rsel = 0; rsel < 2; rsel++) {
            int rloc = warpM * 32 + mi * 16 + gid + rsel * 8;
            int tok = sTok[rloc];
            if (tok < 0) continue;
#pragma unroll
            for (int ni = 0; ni < 4; ni++) {
                int cloc = warpN * 32 + ni * 8 + tig * 2;
                float2 bv = *(const float2*)(bias + cloc);
                float v0 = acc[mi][ni][rsel * 2 + 0] + bv.x;
                float v1 = acc[mi][ni][rsel * 2 + 1] + bv.y;
                if (MODE == 0) {
                    v0 = v0 > 0.f ? v0 : 0.f;
                    v1 = v1 > 0.f ? v1 : 0.f;
                    __half h0 = __float2half_rn(v0);
                    __half h1 = __float2half_rn(v1);
                    __half2 H = {h0, h1};
                    __half2 L = {__float2half_rn(v0 - __half2float(h0)),
                                 __float2half_rn(v1 - __half2float(h1))};
                    size_t o = ((size_t)e * CAP + rowBase + rloc) * DHID + colBase + cloc;
                    *(uint32_t*)(g_hHi + o) = *(uint32_t*)&H;
                    *(uint32_t*)(g_hLo + o) = *(uint32_t*)&L;
                } else {
                    float* op = outg + (size_t)tok * DMODEL + colBase + cloc;
                    *(float2*)op = make_float2(v0, v1);
                }
            }
        }
    }
}

// ---------------- launch ----------------------------------------------------
extern "C" void kernel_launch(void* const* d_in, const int* in_sizes, int n_in,
                              void* d_out, int out_size) {
    const float* x  = (const float*)d_in[0];
    const float* Wg = (const float*)d_in[1];
    const float* bg = (const float*)d_in[2];
    const float* W1 = (const float*)d_in[3];
    const float* b1 = (const float*)d_in[4];
    const float* W2 = (const float*)d_in[5];
    const float* b2 = (const float*)d_in[6];
    float* out = (float*)d_out;

    cudaFuncSetAttribute(moe_ffn<0>, cudaFuncAttributeMaxDynamicSharedMemorySize, FFN_SMEM);
    cudaFuncSetAttribute(moe_ffn<1>, cudaFuncAttributeMaxDynamicSharedMemorySize, FFN_SMEM);

    cudaMemsetAsync(d_out, 0, (size_t)out_size * sizeof(float));

    moe_router<<<NTOK / 8, 256>>>(x, Wg, bg);
    moe_scan<<<1, 256>>>();
    convert_x_f16<<<(NTOK * DMODEL) / 1024, 256>>>(x);
    convert_w_f16<<<(NEXP * DMODEL * DHID) / 1024, 256>>>(W1, 0);
    convert_w_f16<<<(NEXP * DHID * DMODEL) / 1024, 256>>>(W2, 1);

    moe_ffn<0><<<dim3(DHID / BN, CAP / BM, NEXP), 512, FFN_SMEM>>>(b1, nullptr);
    moe_ffn<1><<<dim3(DMODEL / BN, CAP / BM, NEXP), 512, FFN_SMEM>>>(b2, out);
}

// round 11
// speedup vs baseline: 1.9784x; 1.3852x over previous
#include <cuda_runtime.h>
#include <cuda_fp16.h>
#include <cstdint>

// Problem constants (fixed by the reference)
#define NTOK   8192
#define DMODEL 1024
#define DHID   4096
#define NEXP   8
#define CAP    2048

// ---------------- scratch (allocation-free: __device__ globals) ------------
__device__ int   g_route[NTOK];
__device__ int   g_toklist[NEXP * CAP];
__device__ int   g_count[NEXP];

// single-plane fp16 operands
__device__ __align__(16) __half g_xH[(size_t)NTOK * DMODEL];
__device__ __align__(16) __half g_w1H[(size_t)NEXP * DMODEL * DHID];  // [e][k][n]
__device__ __align__(16) __half g_w2H[(size_t)NEXP * DHID * DMODEL];  // [e][k][n]
__device__ __align__(16) __half g_hH[(size_t)NEXP * CAP * DHID];      // [e][row][k]

// ---------------- PTX helpers ----------------------------------------------
__device__ __forceinline__ uint32_t smem_u32(const void* p) {
    return (uint32_t)__cvta_generic_to_shared(p);
}

__device__ __forceinline__ void mma_f16(float* c, const uint32_t* a, const uint32_t* b) {
    asm volatile(
        "mma.sync.aligned.m16n8k16.row.col.f32.f16.f16.f32 "
        "{%0,%1,%2,%3}, {%4,%5,%6,%7}, {%8,%9}, {%0,%1,%2,%3};"
        : "+f"(c[0]), "+f"(c[1]), "+f"(c[2]), "+f"(c[3])
        : "r"(a[0]), "r"(a[1]), "r"(a[2]), "r"(a[3]), "r"(b[0]), "r"(b[1]));
}

__device__ __forceinline__ void ldsm_x4_t(uint32_t& r0, uint32_t& r1,
                                          uint32_t& r2, uint32_t& r3, uint32_t addr) {
    asm volatile("ldmatrix.sync.aligned.m8n8.x4.trans.shared.b16 {%0,%1,%2,%3}, [%4];"
        : "=r"(r0), "=r"(r1), "=r"(r2), "=r"(r3) : "r"(addr));
}

// B tile byte offset with XOR swizzle (k row = 256B; spread bits[6:4] by k&7)
__device__ __forceinline__ uint32_t bswz(int k, int nbyte) {
    return (uint32_t)(k * 256 + (nbyte ^ ((k & 7) << 4)));
}

__device__ __forceinline__ void cp_async16(uint32_t dst, const void* src, int srcSize) {
    asm volatile("cp.async.cg.shared.global [%0], [%1], 16, %2;"
        :: "r"(dst), "l"(src), "r"(srcSize) : "memory");
}
#define CP_COMMIT() asm volatile("cp.async.commit_group;" ::: "memory")
#define CP_WAIT1()  asm volatile("cp.async.wait_group 1;" ::: "memory")

// ---------------- router: logits + argmax (top_k = 1) ---------------------
__global__ __launch_bounds__(256) void moe_router(const float* __restrict__ x,
                                                  const float* __restrict__ Wg,
                                                  const float* __restrict__ bg) {
    __shared__ float sWgT[NEXP][DMODEL];
    int tid = threadIdx.x;
    for (int i = tid; i < DMODEL * NEXP; i += 256) {
        int d = i >> 3, e = i & 7;
        sWgT[e][d] = Wg[i];
    }
    __syncthreads();

    int wid = tid >> 5, lane = tid & 31;
    int token = blockIdx.x * 8 + wid;
    const float* xr = x + (size_t)token * DMODEL;

    float acc[NEXP];
#pragma unroll
    for (int e = 0; e < NEXP; e++) acc[e] = 0.f;
    for (int d = lane; d < DMODEL; d += 32) {
        float xv = xr[d];
#pragma unroll
        for (int e = 0; e < NEXP; e++) acc[e] += xv * sWgT[e][d];
    }
#pragma unroll
    for (int e = 0; e < NEXP; e++) {
#pragma unroll
        for (int off = 16; off > 0; off >>= 1)
            acc[e] += __shfl_xor_sync(0xffffffffu, acc[e], off);
    }
    if (lane == 0) {
        int best = 0;
        float bv = acc[0] + bg[0];
#pragma unroll
        for (int e = 1; e < NEXP; e++) {
            float v = acc[e] + bg[e];
            if (v > bv) { bv = v; best = e; }   // first-max tie-break
        }
        g_route[token] = best;
    }
}

// ---------------- ordered capacity scan ------------------------------------
__global__ __launch_bounds__(256) void moe_scan() {
    int tid = threadIdx.x;
    for (int i = tid; i < NEXP * CAP; i += 256) g_toklist[i] = -1;
    __syncthreads();
    int wid = tid >> 5, lane = tid & 31;   // wid == expert id
    int base = 0;
    for (int c = 0; c < NTOK / 32; c++) {
        int token = c * 32 + lane;
        int r = g_route[token];
        unsigned mask = __ballot_sync(0xffffffffu, r == wid);
        if (r == wid) {
            int pos = base + __popc(mask & ((1u << lane) - 1u));
            if (pos < CAP) g_toklist[wid * CAP + pos] = token;
        }
        base += __popc(mask);
    }
    if (lane == 0) g_count[wid] = base < CAP ? base : CAP;
}

// ---------------- fp32 -> fp16 converts (dest chosen DEVICE-SIDE) -----------
// __device__ array symbols must never be passed as kernel args from host code
// (host shadow address + GB300 ATS silently writes host memory).
__global__ __launch_bounds__(256) void convert_f16(const float* __restrict__ src,
                                                   int which) {
    __half* d = (which == 0) ? g_xH : (which == 1) ? g_w1H : g_w2H;
    size_t i = ((size_t)blockIdx.x * 256 + threadIdx.x) * 4;
    float4 v = *(const float4*)(src + i);
    __half2 H0 = {__float2half_rn(v.x), __float2half_rn(v.y)};
    __half2 H1 = {__float2half_rn(v.z), __float2half_rn(v.w)};
    *(uint2*)(d + i) = make_uint2(*(uint32_t*)&H0, *(uint32_t*)&H1);
}

// ---------------- single-pass fp16 tensor-core GEMMs, 512 threads -----------
// Block tile 128x128, BK=32, cp.async 3-stage pipeline.
// 16 warps in a 4(M) x 4(N) grid; each warp computes 32x32 via 2 m16 x 4 n8
// tiles, fp16 inputs, fp32 accumulate. 16 MMAs per warp per stage.

#define BM 128
#define BN 128
#define BK 32
#define A_STRIDE 40                    // fp16 units per A row (80B)
#define A_PLANE  (BM * A_STRIDE * 2)   // 10240 B
#define B_PLANE  (BK * 256)            // 8192 B
#define STAGE_B  (A_PLANE + B_PLANE)   // 18432 B
#define NSTAGE   3
#define FFN_SMEM (NSTAGE * STAGE_B)    // 55296 B

template <int MODE>
__global__ __launch_bounds__(512, 1) void moe_ffn(const float* __restrict__ bias_g,
                                                  float* __restrict__ outg) {
    const int Ktot = (MODE == 0) ? DMODEL : DHID;
    const int Ntot = (MODE == 0) ? DHID : DMODEL;

    int e = blockIdx.z;
    int count = g_count[e];
    int rowBase = blockIdx.y * BM;
    if (rowBase >= count) return;
    int colBase = blockIdx.x * BN;

    extern __shared__ __align__(16) char dyn[];
    __shared__ int sTok[BM];

    int tid = threadIdx.x;
    if (tid < BM) {
        int row = rowBase + tid;
        sTok[tid] = (row < count) ? g_toklist[e * CAP + row] : -1;
    }
    __syncthreads();

    const float* bias = bias_g + (size_t)e * Ntot + colBase;
    uint32_t smBase = smem_u32(dyn);

    int warpId = tid >> 5, lane = tid & 31;
    int warpM = warpId & 3;            // M offset *32
    int warpN = warpId >> 2;           // N offset *32
    int gid = lane >> 2, tig = lane & 3;

    int lm_m  = lane >> 3;
    int lm_rr = lane & 7;
    int lm_kd = (lm_m & 1) * 8 + lm_rr;
    int lm_nd = (lm_m >> 1) * 8;

    float acc[2][4][4];
#pragma unroll
    for (int mi = 0; mi < 2; mi++)
#pragma unroll
        for (int ni = 0; ni < 4; ni++)
#pragma unroll
            for (int q = 0; q < 4; q++) acc[mi][ni][q] = 0.f;

    // ---- copy-thread indices (512 threads, 2 cp.async each per stage) ----
    int aRow  = tid >> 2;              // A row (0..127), 4 threads/row
    int aSeg  = (tid & 3) * 8;         // k offset 0,8,16,24 (fp16 units)
    int bRow  = tid >> 4;              // B k row (0..31), 16 threads/row
    int bCol  = (tid & 15) * 8;        // B n offset (fp16 units)

    int tokA = (MODE == 0) ? sTok[aRow] : -1;
    bool aValid = (MODE == 0) ? (tokA >= 0) : ((rowBase + aRow) < count);
    int aSize = aValid ? 16 : 0;
    const __half* aP;
    if (MODE == 0) {
        aP = g_xH + (size_t)(tokA < 0 ? 0 : tokA) * DMODEL;
    } else {
        aP = g_hH + ((size_t)e * CAP + rowBase + aRow) * (size_t)DHID;
    }
    const __half* bP = ((MODE == 0) ? g_w1H : g_w2H)
        + (size_t)e * Ktot * Ntot + (size_t)bRow * Ntot + colBase + bCol;

    uint32_t aDst = (uint32_t)aRow * (A_STRIDE * 2) + (uint32_t)aSeg * 2;  // bytes
    uint32_t bDst = bswz(bRow, bCol * 2);
    const int nIter = Ktot / BK;

    auto issue_stage = [&](int i) {
        uint32_t base = smBase + (uint32_t)(i % NSTAGE) * STAGE_B;
        int k0 = i * BK;
        cp_async16(base + aDst,           aP + k0 + aSeg, aSize);
        cp_async16(base + A_PLANE + bDst, bP + (size_t)k0 * Ntot, 16);
    };

    issue_stage(0); CP_COMMIT();
    issue_stage(1); CP_COMMIT();

    for (int i = 0; i < nIter; i++) {
        CP_WAIT1();            // stage i landed
        __syncthreads();
        if (i + 2 < nIter) issue_stage(i + 2);
        CP_COMMIT();

        uint32_t base = smBase + (uint32_t)(i % NSTAGE) * STAGE_B;
        const __half* As = (const __half*)(dyn + (i % NSTAGE) * STAGE_B);
        uint32_t pB = base + A_PLANE;

#pragma unroll
        for (int s = 0; s < 2; s++) {
            int kk = s * 16;
            // ---- A fragments (validated direct-LDS path) ----
            uint32_t aF[2][4];
#pragma unroll
            for (int mi = 0; mi < 2; mi++) {
                int r0 = (warpM * 32 + mi * 16 + gid) * A_STRIDE + kk + 2 * tig;
                int r1 = r0 + 8 * A_STRIDE;
                aF[mi][0] = *(const uint32_t*)&As[r0];
                aF[mi][1] = *(const uint32_t*)&As[r1];
                aF[mi][2] = *(const uint32_t*)&As[r0 + 8];
                aF[mi][3] = *(const uint32_t*)&As[r1 + 8];
            }
            // ---- B fragments: warp covers 32 cols = 2 x n16 panels ----
            uint32_t bh[2][4];
#pragma unroll
            for (int u = 0; u < 2; u++) {
                int n0 = warpN * 32 + u * 16;
                uint32_t off = bswz(kk + lm_kd, (n0 + lm_nd) * 2);
                ldsm_x4_t(bh[u][0], bh[u][1], bh[u][2], bh[u][3], pB + off);
            }
            // ---- MMAs (no consecutive RAW: 8 distinct accumulators) ----
#pragma unroll
            for (int ni = 0; ni < 4; ni++) {
                uint32_t bp[2] = { bh[ni >> 1][(ni & 1) * 2], bh[ni >> 1][(ni & 1) * 2 + 1] };
#pragma unroll
                for (int mi = 0; mi < 2; mi++) mma_f16(acc[mi][ni], aF[mi], bp);
            }
        }
        __syncthreads();       // all reads of stage i done before it is rewritten
    }

    // ---- epilogue ----
#pragma unroll
    for (int mi = 0; mi < 2; mi++) {
#pragma unroll
        for (int rsel = 0; rsel < 2; rsel++) {
            int rloc = warpM * 32 + mi * 16 + gid + rsel * 8;
            int tok = sTok[rloc];
            if (tok < 0) continue;
#pragma unroll
            for (int ni = 0; ni < 4; ni++) {
                int cloc = warpN * 32 + ni * 8 + tig * 2;
                float2 bv = *(const float2*)(bias + cloc);
                float v0 = acc[mi][ni][rsel * 2 + 0] + bv.x;
                float v1 = acc[mi][ni][rsel * 2 + 1] + bv.y;
                if (MODE == 0) {
                    v0 = v0 > 0.f ? v0 : 0.f;
                    v1 = v1 > 0.f ? v1 : 0.f;
                    __half2 H = {__float2half_rn(v0), __float2half_rn(v1)};
                    size_t o = ((size_t)e * CAP + rowBase + rloc) * DHID + colBase + cloc;
                    *(uint32_t*)(g_hH + o) = *(uint32_t*)&H;
                } else {
                    float* op = outg + (size_t)tok * DMODEL + colBase + cloc;
                    *(float2*)op = make_float2(v0, v1);
                }
            }
        }
    }
}

// ---------------- launch ----------------------------------------------------
extern "C" void kernel_launch(void* const* d_in, const int* in_sizes, int n_in,
                              void* d_out, int out_size) {
    const float* x  = (const float*)d_in[0];
    const float* Wg = (const float*)d_in[1];
    const float* bg = (const float*)d_in[2];
    const float* W1 = (const float*)d_in[3];
    const float* b1 = (const float*)d_in[4];
    const float* W2 = (const float*)d_in[5];
    const float* b2 = (const float*)d_in[6];
    float* out = (float*)d_out;

    cudaFuncSetAttribute(moe_ffn<0>, cudaFuncAttributeMaxDynamicSharedMemorySize, FFN_SMEM);
    cudaFuncSetAttribute(moe_ffn<1>, cudaFuncAttributeMaxDynamicSharedMemorySize, FFN_SMEM);

    cudaMemsetAsync(d_out, 0, (size_t)out_size * sizeof(float));

    moe_router<<<NTOK / 8, 256>>>(x, Wg, bg);
    moe_scan<<<1, 256>>>();
    convert_f16<<<(NTOK * DMODEL) / 1024, 256>>>(x, 0);
    convert_f16<<<(NEXP * DMODEL * DHID) / 1024, 256>>>(W1, 1);
    convert_f16<<<(NEXP * DHID * DMODEL) / 1024, 256>>>(W2, 2);

    moe_ffn<0><<<dim3(DHID / BN, CAP / BM, NEXP), 512, FFN_SMEM>>>(b1, nullptr);
    moe_ffn<1><<<dim3(DMODEL / BN, CAP / BM, NEXP), 512, FFN_SMEM>>>(b2, out);
}

// round 12
// speedup vs baseline: 2.1892x; 1.1066x over previous
#include <cuda_runtime.h>
#include <cuda_fp16.h>
#include <cstdint>

// Problem constants (fixed by the reference)
#define NTOK   8192
#define DMODEL 1024
#define DHID   4096
#define NEXP   8
#define CAP    2048

// ---------------- scratch (allocation-free: __device__ globals) ------------
__device__ int   g_route[NTOK];
__device__ int   g_toklist[NEXP * CAP];
__device__ int   g_count[NEXP];

// single-plane fp16 operands
__device__ __align__(16) __half g_xH[(size_t)NTOK * DMODEL];
__device__ __align__(16) __half g_w1H[(size_t)NEXP * DMODEL * DHID];  // [e][k][n]
__device__ __align__(16) __half g_w2H[(size_t)NEXP * DHID * DMODEL];  // [e][k][n]
__device__ __align__(16) __half g_hH[(size_t)NEXP * CAP * DHID];      // [e][row][k]

// ---------------- PTX helpers ----------------------------------------------
__device__ __forceinline__ uint32_t smem_u32(const void* p) {
    return (uint32_t)__cvta_generic_to_shared(p);
}

__device__ __forceinline__ void mma_f16(float* c, const uint32_t* a, const uint32_t* b) {
    asm volatile(
        "mma.sync.aligned.m16n8k16.row.col.f32.f16.f16.f32 "
        "{%0,%1,%2,%3}, {%4,%5,%6,%7}, {%8,%9}, {%0,%1,%2,%3};"
        : "+f"(c[0]), "+f"(c[1]), "+f"(c[2]), "+f"(c[3])
        : "r"(a[0]), "r"(a[1]), "r"(a[2]), "r"(a[3]), "r"(b[0]), "r"(b[1]));
}

__device__ __forceinline__ void ldsm_x4_t(uint32_t& r0, uint32_t& r1,
                                          uint32_t& r2, uint32_t& r3, uint32_t addr) {
    asm volatile("ldmatrix.sync.aligned.m8n8.x4.trans.shared.b16 {%0,%1,%2,%3}, [%4];"
        : "=r"(r0), "=r"(r1), "=r"(r2), "=r"(r3) : "r"(addr));
}

// B tile byte offset with XOR swizzle (k row = 256B; spread bits[6:4] by k&7)
__device__ __forceinline__ uint32_t bswz(int k, int nbyte) {
    return (uint32_t)(k * 256 + (nbyte ^ ((k & 7) << 4)));
}

__device__ __forceinline__ void cp_async16(uint32_t dst, const void* src, int srcSize) {
    asm volatile("cp.async.cg.shared.global [%0], [%1], 16, %2;"
        :: "r"(dst), "l"(src), "r"(srcSize) : "memory");
}
#define CP_COMMIT() asm volatile("cp.async.commit_group;" ::: "memory")
#define CP_WAIT1()  asm volatile("cp.async.wait_group 1;" ::: "memory")

// ---------------- router: logits + argmax (top_k = 1) ---------------------
__global__ __launch_bounds__(256) void moe_router(const float* __restrict__ x,
                                                  const float* __restrict__ Wg,
                                                  const float* __restrict__ bg) {
    __shared__ float sWgT[NEXP][DMODEL];
    int tid = threadIdx.x;
    for (int i = tid; i < DMODEL * NEXP; i += 256) {
        int d = i >> 3, e = i & 7;
        sWgT[e][d] = Wg[i];
    }
    __syncthreads();

    int wid = tid >> 5, lane = tid & 31;
    int token = blockIdx.x * 8 + wid;
    const float* xr = x + (size_t)token * DMODEL;

    float acc[NEXP];
#pragma unroll
    for (int e = 0; e < NEXP; e++) acc[e] = 0.f;
    for (int d = lane; d < DMODEL; d += 32) {
        float xv = xr[d];
#pragma unroll
        for (int e = 0; e < NEXP; e++) acc[e] += xv * sWgT[e][d];
    }
#pragma unroll
    for (int e = 0; e < NEXP; e++) {
#pragma unroll
        for (int off = 16; off > 0; off >>= 1)
            acc[e] += __shfl_xor_sync(0xffffffffu, acc[e], off);
    }
    if (lane == 0) {
        int best = 0;
        float bv = acc[0] + bg[0];
#pragma unroll
        for (int e = 1; e < NEXP; e++) {
            float v = acc[e] + bg[e];
            if (v > bv) { bv = v; best = e; }   // first-max tie-break
        }
        g_route[token] = best;
    }
}

// ---------------- ordered capacity scan ------------------------------------
__global__ __launch_bounds__(256) void moe_scan() {
    int tid = threadIdx.x;
    for (int i = tid; i < NEXP * CAP; i += 256) g_toklist[i] = -1;
    __syncthreads();
    int wid = tid >> 5, lane = tid & 31;   // wid == expert id
    int base = 0;
    for (int c = 0; c < NTOK / 32; c++) {
        int token = c * 32 + lane;
        int r = g_route[token];
        unsigned mask = __ballot_sync(0xffffffffu, r == wid);
        if (r == wid) {
            int pos = base + __popc(mask & ((1u << lane) - 1u));
            if (pos < CAP) g_toklist[wid * CAP + pos] = token;
        }
        base += __popc(mask);
    }
    if (lane == 0) g_count[wid] = base < CAP ? base : CAP;
}

// ---------------- fp32 -> fp16 converts (dest chosen DEVICE-SIDE) -----------
// __device__ array symbols must never be passed as kernel args from host code
// (host shadow address + GB300 ATS silently writes host memory).
__global__ __launch_bounds__(256) void convert_f16(const float* __restrict__ src,
                                                   int which) {
    __half* d = (which == 0) ? g_xH : (which == 1) ? g_w1H : g_w2H;
    size_t i = ((size_t)blockIdx.x * 256 + threadIdx.x) * 4;
    float4 v = *(const float4*)(src + i);
    __half2 H0 = {__float2half_rn(v.x), __float2half_rn(v.y)};
    __half2 H1 = {__float2half_rn(v.z), __float2half_rn(v.w)};
    *(uint2*)(d + i) = make_uint2(*(uint32_t*)&H0, *(uint32_t*)&H1);
}

// ---------------- single-pass fp16 tensor-core GEMMs, 512 threads -----------
// Block tile 128x128, BK=64, cp.async 3-stage pipeline.
// 16 warps in a 4(M) x 4(N) grid; each warp computes 32x32 via 2 m16 x 4 n8
// tiles, fp16 inputs, fp32 accumulate. 32 MMAs per warp per stage (4 k16 steps)
// so per-stage sync/ramp costs amortize over 2x the MMA work vs BK=32.

#define BM 128
#define BN 128
#define BK 64
#define A_STRIDE 72                    // fp16 units per A row (64 data + 8 pad)
                                       // bank check: word = 36*gid + tig,
                                       // 36g mod 32 = 4g -> 32 distinct words
#define A_PLANE  (BM * A_STRIDE * 2)   // 18432 B
#define B_PLANE  (BK * 256)            // 16384 B
#define STAGE_B  (A_PLANE + B_PLANE)   // 34816 B
#define NSTAGE   3
#define FFN_SMEM (NSTAGE * STAGE_B)    // 104448 B

template <int MODE>
__global__ __launch_bounds__(512, 1) void moe_ffn(const float* __restrict__ bias_g,
                                                  float* __restrict__ outg) {
    const int Ktot = (MODE == 0) ? DMODEL : DHID;
    const int Ntot = (MODE == 0) ? DHID : DMODEL;

    int e = blockIdx.z;
    int count = g_count[e];
    int rowBase = blockIdx.y * BM;
    if (rowBase >= count) return;
    int colBase = blockIdx.x * BN;

    extern __shared__ __align__(16) char dyn[];
    __shared__ int sTok[BM];

    int tid = threadIdx.x;
    if (tid < BM) {
        int row = rowBase + tid;
        sTok[tid] = (row < count) ? g_toklist[e * CAP + row] : -1;
    }
    __syncthreads();

    const float* bias = bias_g + (size_t)e * Ntot + colBase;
    uint32_t smBase = smem_u32(dyn);

    int warpId = tid >> 5, lane = tid & 31;
    int warpM = warpId & 3;            // M offset *32
    int warpN = warpId >> 2;           // N offset *32
    int gid = lane >> 2, tig = lane & 3;

    int lm_m  = lane >> 3;
    int lm_rr = lane & 7;
    int lm_kd = (lm_m & 1) * 8 + lm_rr;
    int lm_nd = (lm_m >> 1) * 8;

    float acc[2][4][4];
#pragma unroll
    for (int mi = 0; mi < 2; mi++)
#pragma unroll
        for (int ni = 0; ni < 4; ni++)
#pragma unroll
            for (int q = 0; q < 4; q++) acc[mi][ni][q] = 0.f;

    // ---- copy-thread indices (512 threads, 4 cp.async each per stage) ----
    int aRow  = tid >> 2;              // A row (0..127), 4 threads/row
    int aSeg  = (tid & 3) * 16;        // k offset 0,16,32,48 (fp16 units)
    int bRow  = tid >> 3;              // B k row (0..63), 8 threads/row
    int bCol  = (tid & 7) * 16;        // B n offset (fp16 units)

    int tokA = (MODE == 0) ? sTok[aRow] : -1;
    bool aValid = (MODE == 0) ? (tokA >= 0) : ((rowBase + aRow) < count);
    int aSize = aValid ? 16 : 0;
    const __half* aP;
    if (MODE == 0) {
        aP = g_xH + (size_t)(tokA < 0 ? 0 : tokA) * DMODEL;
    } else {
        aP = g_hH + ((size_t)e * CAP + rowBase + aRow) * (size_t)DHID;
    }
    const __half* bP = ((MODE == 0) ? g_w1H : g_w2H)
        + (size_t)e * Ktot * Ntot + (size_t)bRow * Ntot + colBase + bCol;

    uint32_t aDst  = (uint32_t)aRow * (A_STRIDE * 2) + (uint32_t)aSeg * 2;  // bytes
    uint32_t bDst0 = bswz(bRow, bCol * 2);
    uint32_t bDst1 = bswz(bRow, bCol * 2 + 16);
    const int nIter = Ktot / BK;

    auto issue_stage = [&](int i) {
        uint32_t base = smBase + (uint32_t)(i % NSTAGE) * STAGE_B;
        int k0 = i * BK;
        const __half* bSrc = bP + (size_t)k0 * Ntot;
        cp_async16(base + aDst,                aP + k0 + aSeg,     aSize);
        cp_async16(base + aDst + 16u,          aP + k0 + aSeg + 8, aSize);
        cp_async16(base + A_PLANE + bDst0,     bSrc,               16);
        cp_async16(base + A_PLANE + bDst1,     bSrc + 8,           16);
    };

    issue_stage(0); CP_COMMIT();
    issue_stage(1); CP_COMMIT();

    for (int i = 0; i < nIter; i++) {
        CP_WAIT1();            // stage i landed
        __syncthreads();
        if (i + 2 < nIter) issue_stage(i + 2);
        CP_COMMIT();

        uint32_t base = smBase + (uint32_t)(i % NSTAGE) * STAGE_B;
        const __half* As = (const __half*)(dyn + (i % NSTAGE) * STAGE_B);
        uint32_t pB = base + A_PLANE;

#pragma unroll
        for (int s = 0; s < 4; s++) {
            int kk = s * 16;
            // ---- A fragments (validated direct-LDS path) ----
            uint32_t aF[2][4];
#pragma unroll
            for (int mi = 0; mi < 2; mi++) {
                int r0 = (warpM * 32 + mi * 16 + gid) * A_STRIDE + kk + 2 * tig;
                int r1 = r0 + 8 * A_STRIDE;
                aF[mi][0] = *(const uint32_t*)&As[r0];
                aF[mi][1] = *(const uint32_t*)&As[r1];
                aF[mi][2] = *(const uint32_t*)&As[r0 + 8];
                aF[mi][3] = *(const uint32_t*)&As[r1 + 8];
            }
            // ---- B fragments: warp covers 32 cols = 2 x n16 panels ----
            uint32_t bh[2][4];
#pragma unroll
            for (int u = 0; u < 2; u++) {
                int n0 = warpN * 32 + u * 16;
                uint32_t off = bswz(kk + lm_kd, (n0 + lm_nd) * 2);
                ldsm_x4_t(bh[u][0], bh[u][1], bh[u][2], bh[u][3], pB + off);
            }
            // ---- MMAs (no consecutive RAW: 8 distinct accumulators) ----
#pragma unroll
            for (int ni = 0; ni < 4; ni++) {
                uint32_t bp[2] = { bh[ni >> 1][(ni & 1) * 2], bh[ni >> 1][(ni & 1) * 2 + 1] };
#pragma unroll
                for (int mi = 0; mi < 2; mi++) mma_f16(acc[mi][ni], aF[mi], bp);
            }
        }
        __syncthreads();       // all reads of stage i done before it is rewritten
    }

    // ---- epilogue ----
#pragma unroll
    for (int mi = 0; mi < 2; mi++) {
#pragma unroll
        for (int rsel = 0; rsel < 2; rsel++) {
            int rloc = warpM * 32 + mi * 16 + gid + rsel * 8;
            int tok = sTok[rloc];
            if (tok < 0) continue;
#pragma unroll
            for (int ni = 0; ni < 4; ni++) {
                int cloc = warpN * 32 + ni * 8 + tig * 2;
                float2 bv = *(const float2*)(bias + cloc);
                float v0 = acc[mi][ni][rsel * 2 + 0] + bv.x;
                float v1 = acc[mi][ni][rsel * 2 + 1] + bv.y;
                if (MODE == 0) {
                    v0 = v0 > 0.f ? v0 : 0.f;
                    v1 = v1 > 0.f ? v1 : 0.f;
                    __half2 H = {__float2half_rn(v0), __float2half_rn(v1)};
                    size_t o = ((size_t)e * CAP + rowBase + rloc) * DHID + colBase + cloc;
                    *(uint32_t*)(g_hH + o) = *(uint32_t*)&H;
                } else {
                    float* op = outg + (size_t)tok * DMODEL + colBase + cloc;
                    *(float2*)op = make_float2(v0, v1);
                }
            }
        }
    }
}

// ---------------- launch ----------------------------------------------------
extern "C" void kernel_launch(void* const* d_in, const int* in_sizes, int n_in,
                              void* d_out, int out_size) {
    const float* x  = (const float*)d_in[0];
    const float* Wg = (const float*)d_in[1];
    const float* bg = (const float*)d_in[2];
    const float* W1 = (const float*)d_in[3];
    const float* b1 = (const float*)d_in[4];
    const float* W2 = (const float*)d_in[5];
    const float* b2 = (const float*)d_in[6];
    float* out = (float*)d_out;

    cudaFuncSetAttribute(moe_ffn<0>, cudaFuncAttributeMaxDynamicSharedMemorySize, FFN_SMEM);
    cudaFuncSetAttribute(moe_ffn<1>, cudaFuncAttributeMaxDynamicSharedMemorySize, FFN_SMEM);

    cudaMemsetAsync(d_out, 0, (size_t)out_size * sizeof(float));

    moe_router<<<NTOK / 8, 256>>>(x, Wg, bg);
    moe_scan<<<1, 256>>>();
    convert_f16<<<(NTOK * DMODEL) / 1024, 256>>>(x, 0);
    convert_f16<<<(NEXP * DMODEL * DHID) / 1024, 256>>>(W1, 1);
    convert_f16<<<(NEXP * DHID * DMODEL) / 1024, 256>>>(W2, 2);

    moe_ffn<0><<<dim3(DHID / BN, CAP / BM, NEXP), 512, FFN_SMEM>>>(b1, nullptr);
    moe_ffn<1><<<dim3(DMODEL / BN, CAP / BM, NEXP), 512, FFN_SMEM>>>(b2, out);
}

// round 13
// speedup vs baseline: 2.3207x; 1.0601x over previous
#include <cuda_runtime.h>
#include <cuda_fp16.h>
#include <cstdint>

// Problem constants (fixed by the reference)
#define NTOK   8192
#define DMODEL 1024
#define DHID   4096
#define NEXP   8
#define CAP    2048

// ---------------- scratch (allocation-free: __device__ globals) ------------
__device__ int   g_route[NTOK];
__device__ int   g_toklist[NEXP * CAP];
__device__ int   g_count[NEXP];

// single-plane fp16 operands
__device__ __align__(16) __half g_xH[(size_t)NTOK * DMODEL];
__device__ __align__(16) __half g_w1H[(size_t)NEXP * DMODEL * DHID];  // [e][k][n]
__device__ __align__(16) __half g_w2H[(size_t)NEXP * DHID * DMODEL];  // [e][k][n]
__device__ __align__(16) __half g_hH[(size_t)NEXP * CAP * DHID];      // [e][row][k]

// ---------------- PTX helpers ----------------------------------------------
__device__ __forceinline__ uint32_t smem_u32(const void* p) {
    return (uint32_t)__cvta_generic_to_shared(p);
}

__device__ __forceinline__ void mma_f16(float* c, const uint32_t* a, const uint32_t* b) {
    asm volatile(
        "mma.sync.aligned.m16n8k16.row.col.f32.f16.f16.f32 "
        "{%0,%1,%2,%3}, {%4,%5,%6,%7}, {%8,%9}, {%0,%1,%2,%3};"
        : "+f"(c[0]), "+f"(c[1]), "+f"(c[2]), "+f"(c[3])
        : "r"(a[0]), "r"(a[1]), "r"(a[2]), "r"(a[3]), "r"(b[0]), "r"(b[1]));
}

__device__ __forceinline__ void ldsm_x4(uint32_t& r0, uint32_t& r1,
                                        uint32_t& r2, uint32_t& r3, uint32_t addr) {
    asm volatile("ldmatrix.sync.aligned.m8n8.x4.shared.b16 {%0,%1,%2,%3}, [%4];"
        : "=r"(r0), "=r"(r1), "=r"(r2), "=r"(r3) : "r"(addr));
}

__device__ __forceinline__ void ldsm_x4_t(uint32_t& r0, uint32_t& r1,
                                          uint32_t& r2, uint32_t& r3, uint32_t addr) {
    asm volatile("ldmatrix.sync.aligned.m8n8.x4.trans.shared.b16 {%0,%1,%2,%3}, [%4];"
        : "=r"(r0), "=r"(r1), "=r"(r2), "=r"(r3) : "r"(addr));
}

// B tile byte offset with XOR swizzle (k row = 256B; spread bits[6:4] by k&7)
__device__ __forceinline__ uint32_t bswz(int k, int nbyte) {
    return (uint32_t)(k * 256 + (nbyte ^ ((k & 7) << 4)));
}

__device__ __forceinline__ void cp_async16(uint32_t dst, const void* src, int srcSize) {
    asm volatile("cp.async.cg.shared.global [%0], [%1], 16, %2;"
        :: "r"(dst), "l"(src), "r"(srcSize) : "memory");
}
#define CP_COMMIT() asm volatile("cp.async.commit_group;" ::: "memory")
#define CP_WAIT2()  asm volatile("cp.async.wait_group 2;" ::: "memory")

// ---------------- router: logits + argmax (top_k = 1) ---------------------
__global__ __launch_bounds__(256) void moe_router(const float* __restrict__ x,
                                                  const float* __restrict__ Wg,
                                                  const float* __restrict__ bg) {
    __shared__ float sWgT[NEXP][DMODEL];
    int tid = threadIdx.x;
    for (int i = tid; i < DMODEL * NEXP; i += 256) {
        int d = i >> 3, e = i & 7;
        sWgT[e][d] = Wg[i];
    }
    __syncthreads();

    int wid = tid >> 5, lane = tid & 31;
    int token = blockIdx.x * 8 + wid;
    const float* xr = x + (size_t)token * DMODEL;

    float acc[NEXP];
#pragma unroll
    for (int e = 0; e < NEXP; e++) acc[e] = 0.f;
    for (int d = lane; d < DMODEL; d += 32) {
        float xv = xr[d];
#pragma unroll
        for (int e = 0; e < NEXP; e++) acc[e] += xv * sWgT[e][d];
    }
#pragma unroll
    for (int e = 0; e < NEXP; e++) {
#pragma unroll
        for (int off = 16; off > 0; off >>= 1)
            acc[e] += __shfl_xor_sync(0xffffffffu, acc[e], off);
    }
    if (lane == 0) {
        int best = 0;
        float bv = acc[0] + bg[0];
#pragma unroll
        for (int e = 1; e < NEXP; e++) {
            float v = acc[e] + bg[e];
            if (v > bv) { bv = v; best = e; }   // first-max tie-break
        }
        g_route[token] = best;
    }
}

// ---------------- ordered capacity scan ------------------------------------
__global__ __launch_bounds__(256) void moe_scan() {
    int tid = threadIdx.x;
    for (int i = tid; i < NEXP * CAP; i += 256) g_toklist[i] = -1;
    __syncthreads();
    int wid = tid >> 5, lane = tid & 31;   // wid == expert id
    int base = 0;
    for (int c = 0; c < NTOK / 32; c++) {
        int token = c * 32 + lane;
        int r = g_route[token];
        unsigned mask = __ballot_sync(0xffffffffu, r == wid);
        if (r == wid) {
            int pos = base + __popc(mask & ((1u << lane) - 1u));
            if (pos < CAP) g_toklist[wid * CAP + pos] = token;
        }
        base += __popc(mask);
    }
    if (lane == 0) g_count[wid] = base < CAP ? base : CAP;
}

// ---------------- fp32 -> fp16 converts (dest chosen DEVICE-SIDE) -----------
// __device__ array symbols must never be passed as kernel args from host code
// (host shadow address + GB300 ATS silently writes host memory).
__global__ __launch_bounds__(256) void convert_f16(const float* __restrict__ src,
                                                   int which) {
    __half* d = (which == 0) ? g_xH : (which == 1) ? g_w1H : g_w2H;
    size_t i = ((size_t)blockIdx.x * 256 + threadIdx.x) * 4;
    float4 v = *(const float4*)(src + i);
    __half2 H0 = {__float2half_rn(v.x), __float2half_rn(v.y)};
    __half2 H1 = {__float2half_rn(v.z), __float2half_rn(v.w)};
    *(uint2*)(d + i) = make_uint2(*(uint32_t*)&H0, *(uint32_t*)&H1);
}

// ---------------- single-pass fp16 tensor-core GEMMs, 512 threads -----------
// Block tile 128x128, BK=64, cp.async 4-stage pipeline (2 stages in flight
// under compute). 16 warps in 4(M) x 4(N); warp = 32x32 via 2 m16 x 4 n8,
// fp16 inputs, fp32 accumulate. A fragments via ldmatrix.x4 (non-trans):
// 2 LDSM replace 8 LDS.32 per k-step.

#define BM 128
#define BN 128
#define BK 64
#define A_STRIDE 72                    // fp16 units per A row (64 data + 8 pad)
                                       // row stride 144B = 36 words; 36g mod 32
                                       // = 4g -> 8 rows/phase hit banks 0,4..28
#define A_PLANE  (BM * A_STRIDE * 2)   // 18432 B
#define B_PLANE  (BK * 256)            // 16384 B
#define STAGE_B  (A_PLANE + B_PLANE)   // 34816 B
#define NSTAGE   4
#define FFN_SMEM (NSTAGE * STAGE_B)    // 139264 B

template <int MODE>
__global__ __launch_bounds__(512, 1) void moe_ffn(const float* __restrict__ bias_g,
                                                  float* __restrict__ outg) {
    const int Ktot = (MODE == 0) ? DMODEL : DHID;
    const int Ntot = (MODE == 0) ? DHID : DMODEL;

    int e = blockIdx.z;
    int count = g_count[e];
    int rowBase = blockIdx.y * BM;
    if (rowBase >= count) return;
    int colBase = blockIdx.x * BN;

    extern __shared__ __align__(16) char dyn[];
    __shared__ int sTok[BM];

    int tid = threadIdx.x;
    if (tid < BM) {
        int row = rowBase + tid;
        sTok[tid] = (row < count) ? g_toklist[e * CAP + row] : -1;
    }
    __syncthreads();

    const float* bias = bias_g + (size_t)e * Ntot + colBase;
    uint32_t smBase = smem_u32(dyn);

    int warpId = tid >> 5, lane = tid & 31;
    int warpM = warpId & 3;            // M offset *32
    int warpN = warpId >> 2;           // N offset *32
    int gid = lane >> 2, tig = lane & 3;

    int lm_m  = lane >> 3;             // matrix index 0..3
    int lm_rr = lane & 7;
    int lm_kd = (lm_m & 1) * 8 + lm_rr;   // B: k offset within k16
    int lm_nd = (lm_m >> 1) * 8;          // B: n offset within n16 panel
    // A ldmatrix lane address components: matrices (rows0-7,kk),(rows8-15,kk),
    // (rows0-7,kk+8),(rows8-15,kk+8) -> r0..r3 = a0..a3 of m16n8k16
    int aLmRow = (lm_m & 1) * 8 + lm_rr;  // row within m16
    int aLmCol = (lm_m >> 1) * 8;         // k offset within k16

    float acc[2][4][4];
#pragma unroll
    for (int mi = 0; mi < 2; mi++)
#pragma unroll
        for (int ni = 0; ni < 4; ni++)
#pragma unroll
            for (int q = 0; q < 4; q++) acc[mi][ni][q] = 0.f;

    // ---- copy-thread indices (512 threads, 4 cp.async each per stage) ----
    int aRow  = tid >> 2;              // A row (0..127), 4 threads/row
    int aSeg  = (tid & 3) * 16;        // k offset 0,16,32,48 (fp16 units)
    int bRow  = tid >> 3;              // B k row (0..63), 8 threads/row
    int bCol  = (tid & 7) * 16;        // B n offset (fp16 units)

    int tokA = (MODE == 0) ? sTok[aRow] : -1;
    bool aValid = (MODE == 0) ? (tokA >= 0) : ((rowBase + aRow) < count);
    int aSize = aValid ? 16 : 0;
    const __half* aP;
    if (MODE == 0) {
        aP = g_xH + (size_t)(tokA < 0 ? 0 : tokA) * DMODEL;
    } else {
        aP = g_hH + ((size_t)e * CAP + rowBase + aRow) * (size_t)DHID;
    }
    const __half* bP = ((MODE == 0) ? g_w1H : g_w2H)
        + (size_t)e * Ktot * Ntot + (size_t)bRow * Ntot + colBase + bCol;

    uint32_t aDst  = (uint32_t)aRow * (A_STRIDE * 2) + (uint32_t)aSeg * 2;  // bytes
    uint32_t bDst0 = bswz(bRow, bCol * 2);
    uint32_t bDst1 = bswz(bRow, bCol * 2 + 16);
    const int nIter = Ktot / BK;

    auto issue_stage = [&](int i) {
        uint32_t base = smBase + (uint32_t)(i % NSTAGE) * STAGE_B;
        int k0 = i * BK;
        const __half* bSrc = bP + (size_t)k0 * Ntot;
        cp_async16(base + aDst,            aP + k0 + aSeg,     aSize);
        cp_async16(base + aDst + 16u,      aP + k0 + aSeg + 8, aSize);
        cp_async16(base + A_PLANE + bDst0, bSrc,               16);
        cp_async16(base + A_PLANE + bDst1, bSrc + 8,           16);
    };

    issue_stage(0); CP_COMMIT();
    issue_stage(1); CP_COMMIT();
    issue_stage(2); CP_COMMIT();

    for (int i = 0; i < nIter; i++) {
        CP_WAIT2();            // stage i landed (<= 2 newer groups pending)
        __syncthreads();
        if (i + 3 < nIter) issue_stage(i + 3);
        CP_COMMIT();

        uint32_t base = smBase + (uint32_t)(i % NSTAGE) * STAGE_B;
        uint32_t pA = base;
        uint32_t pB = base + A_PLANE;

#pragma unroll
        for (int s = 0; s < 4; s++) {
            int kk = s * 16;
            // ---- A fragments via ldmatrix.x4 (non-trans) ----
            uint32_t aF[2][4];
#pragma unroll
            for (int mi = 0; mi < 2; mi++) {
                uint32_t ao = pA + (uint32_t)(((warpM * 32 + mi * 16 + aLmRow) * A_STRIDE
                                               + kk + aLmCol) * 2);
                ldsm_x4(aF[mi][0], aF[mi][1], aF[mi][2], aF[mi][3], ao);
            }
            // ---- B fragments: warp covers 32 cols = 2 x n16 panels ----
            uint32_t bh[2][4];
#pragma unroll
            for (int u = 0; u < 2; u++) {
                int n0 = warpN * 32 + u * 16;
                uint32_t off = bswz(kk + lm_kd, (n0 + lm_nd) * 2);
                ldsm_x4_t(bh[u][0], bh[u][1], bh[u][2], bh[u][3], pB + off);
            }
            // ---- MMAs (no consecutive RAW: 8 distinct accumulators) ----
#pragma unroll
            for (int ni = 0; ni < 4; ni++) {
                uint32_t bp[2] = { bh[ni >> 1][(ni & 1) * 2], bh[ni >> 1][(ni & 1) * 2 + 1] };
#pragma unroll
                for (int mi = 0; mi < 2; mi++) mma_f16(acc[mi][ni], aF[mi], bp);
            }
        }
        __syncthreads();       // all reads of stage i done before it is rewritten
    }

    // ---- epilogue ----
#pragma unroll
    for (int mi = 0; mi < 2; mi++) {
#pragma unroll
        for (int rsel = 0; rsel < 2; rsel++) {
            int rloc = warpM * 32 + mi * 16 + gid + rsel * 8;
            int tok = sTok[rloc];
            if (tok < 0) continue;
#pragma unroll
            for (int ni = 0; ni < 4; ni++) {
                int cloc = warpN * 32 + ni * 8 + tig * 2;
                float2 bv = *(const float2*)(bias + cloc);
                float v0 = acc[mi][ni][rsel * 2 + 0] + bv.x;
                float v1 = acc[mi][ni][rsel * 2 + 1] + bv.y;
                if (MODE == 0) {
                    v0 = v0 > 0.f ? v0 : 0.f;
                    v1 = v1 > 0.f ? v1 : 0.f;
                    __half2 H = {__float2half_rn(v0), __float2half_rn(v1)};
                    size_t o = ((size_t)e * CAP + rowBase + rloc) * DHID + colBase + cloc;
                    *(uint32_t*)(g_hH + o) = *(uint32_t*)&H;
                } else {
                    float* op = outg + (size_t)tok * DMODEL + colBase + cloc;
                    *(float2*)op = make_float2(v0, v1);
                }
            }
        }
    }
}

// ---------------- launch ----------------------------------------------------
extern "C" void kernel_launch(void* const* d_in, const int* in_sizes, int n_in,
                              void* d_out, int out_size) {
    const float* x  = (const float*)d_in[0];
    const float* Wg = (const float*)d_in[1];
    const float* bg = (const float*)d_in[2];
    const float* W1 = (const float*)d_in[3];
    const float* b1 = (const float*)d_in[4];
    const float* W2 = (const float*)d_in[5];
    const float* b2 = (const float*)d_in[6];
    float* out = (float*)d_out;

    cudaFuncSetAttribute(moe_ffn<0>, cudaFuncAttributeMaxDynamicSharedMemorySize, FFN_SMEM);
    cudaFuncSetAttribute(moe_ffn<1>, cudaFuncAttributeMaxDynamicSharedMemorySize, FFN_SMEM);

    cudaMemsetAsync(d_out, 0, (size_t)out_size * sizeof(float));

    moe_router<<<NTOK / 8, 256>>>(x, Wg, bg);
    moe_scan<<<1, 256>>>();
    convert_f16<<<(NTOK * DMODEL) / 1024, 256>>>(x, 0);
    convert_f16<<<(NEXP * DMODEL * DHID) / 1024, 256>>>(W1, 1);
    convert_f16<<<(NEXP * DHID * DMODEL) / 1024, 256>>>(W2, 2);

    moe_ffn<0><<<dim3(DHID / BN, CAP / BM, NEXP), 512, FFN_SMEM>>>(b1, nullptr);
    moe_ffn<1><<<dim3(DMODEL / BN, CAP / BM, NEXP), 512, FFN_SMEM>>>(b2, out);
}

// round 14
// speedup vs baseline: 2.7477x; 1.1840x over previous
#include <cuda_runtime.h>
#include <cuda_fp16.h>
#include <cstdint>

// Problem constants (fixed by the reference)
#define NTOK   8192
#define DMODEL 1024
#define DHID   4096
#define NEXP   8
#define CAP    2048

// ---------------- scratch (allocation-free: __device__ globals) ------------
__device__ int   g_route[NTOK];
__device__ int   g_toklist[NEXP * CAP];
__device__ int   g_count[NEXP];

// single-plane fp16 operands
__device__ __align__(16) __half g_xH[(size_t)NTOK * DMODEL];
__device__ __align__(16) __half g_w1H[(size_t)NEXP * DMODEL * DHID];  // [e][k][n]
__device__ __align__(16) __half g_w2H[(size_t)NEXP * DHID * DMODEL];  // [e][k][n]
__device__ __align__(16) __half g_hH[(size_t)NEXP * CAP * DHID];      // [e][row][k]

// ---------------- PTX helpers ----------------------------------------------
__device__ __forceinline__ uint32_t smem_u32(const void* p) {
    return (uint32_t)__cvta_generic_to_shared(p);
}

__device__ __forceinline__ void mma_f16(float* c, const uint32_t* a, const uint32_t* b) {
    asm volatile(
        "mma.sync.aligned.m16n8k16.row.col.f32.f16.f16.f32 "
        "{%0,%1,%2,%3}, {%4,%5,%6,%7}, {%8,%9}, {%0,%1,%2,%3};"
        : "+f"(c[0]), "+f"(c[1]), "+f"(c[2]), "+f"(c[3])
        : "r"(a[0]), "r"(a[1]), "r"(a[2]), "r"(a[3]), "r"(b[0]), "r"(b[1]));
}

__device__ __forceinline__ void ldsm_x4(uint32_t& r0, uint32_t& r1,
                                        uint32_t& r2, uint32_t& r3, uint32_t addr) {
    asm volatile("ldmatrix.sync.aligned.m8n8.x4.shared.b16 {%0,%1,%2,%3}, [%4];"
        : "=r"(r0), "=r"(r1), "=r"(r2), "=r"(r3) : "r"(addr));
}

__device__ __forceinline__ void ldsm_x4_t(uint32_t& r0, uint32_t& r1,
                                          uint32_t& r2, uint32_t& r3, uint32_t addr) {
    asm volatile("ldmatrix.sync.aligned.m8n8.x4.trans.shared.b16 {%0,%1,%2,%3}, [%4];"
        : "=r"(r0), "=r"(r1), "=r"(r2), "=r"(r3) : "r"(addr));
}

// B sub-tile byte offset with XOR swizzle (k row = 256B; validated layout)
__device__ __forceinline__ uint32_t bswz(int k, int nbyte) {
    return (uint32_t)(k * 256 + (nbyte ^ ((k & 7) << 4)));
}

__device__ __forceinline__ void cp_async16(uint32_t dst, const void* src, int srcSize) {
    asm volatile("cp.async.cg.shared.global [%0], [%1], 16, %2;"
        :: "r"(dst), "l"(src), "r"(srcSize) : "memory");
}
#define CP_COMMIT() asm volatile("cp.async.commit_group;" ::: "memory")
#define CP_WAIT2()  asm volatile("cp.async.wait_group 2;" ::: "memory")

// ---------------- router: logits + argmax (top_k = 1) ---------------------
__global__ __launch_bounds__(256) void moe_router(const float* __restrict__ x,
                                                  const float* __restrict__ Wg,
                                                  const float* __restrict__ bg) {
    __shared__ float sWgT[NEXP][DMODEL];
    int tid = threadIdx.x;
    for (int i = tid; i < DMODEL * NEXP; i += 256) {
        int d = i >> 3, e = i & 7;
        sWgT[e][d] = Wg[i];
    }
    __syncthreads();

    int wid = tid >> 5, lane = tid & 31;
    int token = blockIdx.x * 8 + wid;
    const float* xr = x + (size_t)token * DMODEL;

    float acc[NEXP];
#pragma unroll
    for (int e = 0; e < NEXP; e++) acc[e] = 0.f;
    for (int d = lane; d < DMODEL; d += 32) {
        float xv = xr[d];
#pragma unroll
        for (int e = 0; e < NEXP; e++) acc[e] += xv * sWgT[e][d];
    }
#pragma unroll
    for (int e = 0; e < NEXP; e++) {
#pragma unroll
        for (int off = 16; off > 0; off >>= 1)
            acc[e] += __shfl_xor_sync(0xffffffffu, acc[e], off);
    }
    if (lane == 0) {
        int best = 0;
        float bv = acc[0] + bg[0];
#pragma unroll
        for (int e = 1; e < NEXP; e++) {
            float v = acc[e] + bg[e];
            if (v > bv) { bv = v; best = e; }   // first-max tie-break
        }
        g_route[token] = best;
    }
}

// ---------------- ordered capacity scan ------------------------------------
__global__ __launch_bounds__(256) void moe_scan() {
    int tid = threadIdx.x;
    for (int i = tid; i < NEXP * CAP; i += 256) g_toklist[i] = -1;
    __syncthreads();
    int wid = tid >> 5, lane = tid & 31;   // wid == expert id
    int base = 0;
    for (int c = 0; c < NTOK / 32; c++) {
        int token = c * 32 + lane;
        int r = g_route[token];
        unsigned mask = __ballot_sync(0xffffffffu, r == wid);
        if (r == wid) {
            int pos = base + __popc(mask & ((1u << lane) - 1u));
            if (pos < CAP) g_toklist[wid * CAP + pos] = token;
        }
        base += __popc(mask);
    }
    if (lane == 0) g_count[wid] = base < CAP ? base : CAP;
}

// ---------------- fp32 -> fp16 converts (dest chosen DEVICE-SIDE) -----------
// __device__ array symbols must never be passed as kernel args from host code
// (host shadow address + GB300 ATS silently writes host memory).
__global__ __launch_bounds__(256) void convert_f16(const float* __restrict__ src,
                                                   int which) {
    __half* d = (which == 0) ? g_xH : (which == 1) ? g_w1H : g_w2H;
    size_t i = ((size_t)blockIdx.x * 256 + threadIdx.x) * 4;
    float4 v = *(const float4*)(src + i);
    __half2 H0 = {__float2half_rn(v.x), __float2half_rn(v.y)};
    __half2 H1 = {__float2half_rn(v.z), __float2half_rn(v.w)};
    *(uint2*)(d + i) = make_uint2(*(uint32_t*)&H0, *(uint32_t*)&H1);
}

// ---------------- single-pass fp16 tensor-core GEMMs, 512 threads -----------
// Block tile 128x256, BK=64, cp.async 4-stage pipeline. 16 warps in a
// 4(M) x 4(N) grid; warp tile 32x64 via 2 m16 x 8 n8, fp16 in, fp32 acc.
// Per k16 step: 2 A-LDSM + 4 B-LDSM + 16 MMA (LDSM tax ~25% lower than 32x32).
// B tile = two independent 128-col sub-tiles, each using the VALIDATED
// 256B-row bswz layout.

#define BM 128
#define BN 256
#define BK 64
#define A_STRIDE 72                    // fp16 units per A row (64 data + 8 pad)
#define A_PLANE  (BM * A_STRIDE * 2)   // 18432 B
#define SUBB     (BK * 256)            // 16384 B per 128-col sub-tile
#define B_PLANE  (2 * SUBB)            // 32768 B
#define STAGE_B  (A_PLANE + B_PLANE)   // 51200 B
#define NSTAGE   4
#define FFN_SMEM (NSTAGE * STAGE_B)    // 204800 B

template <int MODE>
__global__ __launch_bounds__(512, 1) void moe_ffn(const float* __restrict__ bias_g,
                                                  float* __restrict__ outg) {
    const int Ktot = (MODE == 0) ? DMODEL : DHID;
    const int Ntot = (MODE == 0) ? DHID : DMODEL;

    int e = blockIdx.z;
    int count = g_count[e];
    int rowBase = blockIdx.y * BM;
    if (rowBase >= count) return;
    int colBase = blockIdx.x * BN;

    extern __shared__ __align__(16) char dyn[];
    __shared__ int sTok[BM];

    int tid = threadIdx.x;
    if (tid < BM) {
        int row = rowBase + tid;
        sTok[tid] = (row < count) ? g_toklist[e * CAP + row] : -1;
    }
    __syncthreads();

    const float* bias = bias_g + (size_t)e * Ntot + colBase;
    uint32_t smBase = smem_u32(dyn);

    int warpId = tid >> 5, lane = tid & 31;
    int warpM = warpId & 3;            // M offset *32
    int warpN = warpId >> 2;           // N offset *64
    int gid = lane >> 2, tig = lane & 3;

    int lm_m  = lane >> 3;             // matrix index 0..3
    int lm_rr = lane & 7;
    int lm_kd = (lm_m & 1) * 8 + lm_rr;   // B: k offset within k16
    int lm_nd = (lm_m >> 1) * 8;          // B: n offset within n16 panel
    int aLmRow = (lm_m & 1) * 8 + lm_rr;  // A: row within m16
    int aLmCol = (lm_m >> 1) * 8;         // A: k offset within k16

    float acc[2][8][4];
#pragma unroll
    for (int mi = 0; mi < 2; mi++)
#pragma unroll
        for (int ni = 0; ni < 8; ni++)
#pragma unroll
            for (int q = 0; q < 4; q++) acc[mi][ni][q] = 0.f;

    // ---- copy-thread indices (512 threads, 6 cp.async each per stage) ----
    int aRow  = tid >> 2;              // A row (0..127), 4 threads/row
    int aSeg  = (tid & 3) * 16;        // k offset 0,16,32,48 (fp16 units)
    int bRow  = tid >> 3;              // B k row (0..63), 8 threads/row
    int bCol  = (tid & 7) * 16;        // B n offset within 128-col sub-tile

    int tokA = (MODE == 0) ? sTok[aRow] : -1;
    bool aValid = (MODE == 0) ? (tokA >= 0) : ((rowBase + aRow) < count);
    int aSize = aValid ? 16 : 0;
    const __half* aP;
    if (MODE == 0) {
        aP = g_xH + (size_t)(tokA < 0 ? 0 : tokA) * DMODEL;
    } else {
        aP = g_hH + ((size_t)e * CAP + rowBase + aRow) * (size_t)DHID;
    }
    const __half* bP = ((MODE == 0) ? g_w1H : g_w2H)
        + (size_t)e * Ktot * Ntot + (size_t)bRow * Ntot + colBase + bCol;

    uint32_t aDst  = (uint32_t)aRow * (A_STRIDE * 2) + (uint32_t)aSeg * 2;  // bytes
    uint32_t bDst0 = bswz(bRow, bCol * 2);
    uint32_t bDst1 = bswz(bRow, bCol * 2 + 16);
    const int nIter = Ktot / BK;

    auto issue_stage = [&](int i) {
        uint32_t base = smBase + (uint32_t)(i % NSTAGE) * STAGE_B;
        int k0 = i * BK;
        const __half* bSrc = bP + (size_t)k0 * Ntot;
        cp_async16(base + aDst,       aP + k0 + aSeg,     aSize);
        cp_async16(base + aDst + 16u, aP + k0 + aSeg + 8, aSize);
        uint32_t bb = base + A_PLANE;
#pragma unroll
        for (int sub = 0; sub < 2; sub++) {           // two 128-col sub-tiles
            cp_async16(bb + bDst0, bSrc,     16);
            cp_async16(bb + bDst1, bSrc + 8, 16);
            bb += SUBB;
            bSrc += 128;
        }
    };

    issue_stage(0); CP_COMMIT();
    issue_stage(1); CP_COMMIT();
    issue_stage(2); CP_COMMIT();

    for (int i = 0; i < nIter; i++) {
        CP_WAIT2();            // stage i landed (<= 2 newer groups pending)
        __syncthreads();
        if (i + 3 < nIter) issue_stage(i + 3);
        CP_COMMIT();

        uint32_t base = smBase + (uint32_t)(i % NSTAGE) * STAGE_B;
        uint32_t pA = base;
        uint32_t pB = base + A_PLANE;

#pragma unroll
        for (int s = 0; s < 4; s++) {
            int kk = s * 16;
            // ---- A fragments via ldmatrix.x4 (non-trans) ----
            uint32_t aF[2][4];
#pragma unroll
            for (int mi = 0; mi < 2; mi++) {
                uint32_t ao = pA + (uint32_t)(((warpM * 32 + mi * 16 + aLmRow) * A_STRIDE
                                               + kk + aLmCol) * 2);
                ldsm_x4(aF[mi][0], aF[mi][1], aF[mi][2], aF[mi][3], ao);
            }
            // ---- B fragments: warp covers 64 cols = 4 x n16 panels ----
            uint32_t bh[4][4];
#pragma unroll
            for (int u = 0; u < 4; u++) {
                int n0 = warpN * 64 + u * 16;
                uint32_t off = (uint32_t)((n0 >> 7) * SUBB)
                             + bswz(kk + lm_kd, ((n0 & 127) + lm_nd) * 2);
                ldsm_x4_t(bh[u][0], bh[u][1], bh[u][2], bh[u][3], pB + off);
            }
            // ---- MMAs (16 distinct accumulators; no consecutive RAW) ----
#pragma unroll
            for (int ni = 0; ni < 8; ni++) {
                uint32_t bp[2] = { bh[ni >> 1][(ni & 1) * 2], bh[ni >> 1][(ni & 1) * 2 + 1] };
#pragma unroll
                for (int mi = 0; mi < 2; mi++) mma_f16(acc[mi][ni], aF[mi], bp);
            }
        }
        __syncthreads();       // all reads of stage i done before it is rewritten
    }

    // ---- epilogue ----
#pragma unroll
    for (int mi = 0; mi < 2; mi++) {
#pragma unroll
        for (int rsel = 0; rsel < 2; rsel++) {
            int rloc = warpM * 32 + mi * 16 + gid + rsel * 8;
            int tok = sTok[rloc];
            if (tok < 0) continue;
#pragma unroll
            for (int ni = 0; ni < 8; ni++) {
                int cloc = warpN * 64 + ni * 8 + tig * 2;
                float2 bv = *(const float2*)(bias + cloc);
                float v0 = acc[mi][ni][rsel * 2 + 0] + bv.x;
                float v1 = acc[mi][ni][rsel * 2 + 1] + bv.y;
                if (MODE == 0) {
                    v0 = v0 > 0.f ? v0 : 0.f;
                    v1 = v1 > 0.f ? v1 : 0.f;
                    __half2 H = {__float2half_rn(v0), __float2half_rn(v1)};
                    size_t o = ((size_t)e * CAP + rowBase + rloc) * DHID + colBase + cloc;
                    *(uint32_t*)(g_hH + o) = *(uint32_t*)&H;
                } else {
                    float* op = outg + (size_t)tok * DMODEL + colBase + cloc;
                    *(float2*)op = make_float2(v0, v1);
                }
            }
        }
    }
}

// ---------------- launch ----------------------------------------------------
extern "C" void kernel_launch(void* const* d_in, const int* in_sizes, int n_in,
                              void* d_out, int out_size) {
    const float* x  = (const float*)d_in[0];
    const float* Wg = (const float*)d_in[1];
    const float* bg = (const float*)d_in[2];
    const float* W1 = (const float*)d_in[3];
    const float* b1 = (const float*)d_in[4];
    const float* W2 = (const float*)d_in[5];
    const float* b2 = (const float*)d_in[6];
    float* out = (float*)d_out;

    cudaFuncSetAttribute(moe_ffn<0>, cudaFuncAttributeMaxDynamicSharedMemorySize, FFN_SMEM);
    cudaFuncSetAttribute(moe_ffn<1>, cudaFuncAttributeMaxDynamicSharedMemorySize, FFN_SMEM);

    cudaMemsetAsync(d_out, 0, (size_t)out_size * sizeof(float));

    moe_router<<<NTOK / 8, 256>>>(x, Wg, bg);
    moe_scan<<<1, 256>>>();
    convert_f16<<<(NTOK * DMODEL) / 1024, 256>>>(x, 0);
    convert_f16<<<(NEXP * DMODEL * DHID) / 1024, 256>>>(W1, 1);
    convert_f16<<<(NEXP * DHID * DMODEL) / 1024, 256>>>(W2, 2);

    moe_ffn<0><<<dim3(DHID / BN, CAP / BM, NEXP), 512, FFN_SMEM>>>(b1, nullptr);
    moe_ffn<1><<<dim3(DMODEL / BN, CAP / BM, NEXP), 512, FFN_SMEM>>>(b2, out);
}